// round 2
// baseline (speedup 1.0000x reference)
#include <cuda_runtime.h>
#include <math.h>

#define NSRC 10000
#define NEDGE 320000
#define DIM 128
#define EDIM 236
#define TOPN 6
#define BN_EPS 1e-5f

// ---------------- scratch (device globals; no allocation allowed) ----------
__device__ float  g_agg[(size_t)NSRC * EDIM];        // segment-summed relu(path_feats)
__device__ float  g_xg[(size_t)NEDGE * DIM];         // path_feats @ pe_tgt_W
__device__ float  g_srcterm[(size_t)NSRC * DIM];     // node_emb@pe_src_W + (pe_src_b+pe_tgt_b)
__device__ float  g_H[(size_t)3 * NSRC * DIM];       // per-conv pre-MLP features
__device__ float  g_T[(size_t)3 * NSRC * DIM];       // per-conv pre-BN activations
__device__ float  g_h2[(size_t)NSRC * DIM];
__device__ float  g_Wc[3 * DIM * DIM];               // conv_W2[i] @ lin1_W[i-block]
__device__ float  g_scores[NEDGE];
__device__ int    g_cnt[NSRC];
__device__ int    g_off[NSRC + 1];
__device__ int    g_cur[NSRC];
__device__ int    g_order[NEDGE];
__device__ double g_tsum[3 * DIM], g_tsumsq[3 * DIM];
__device__ double g_psum[DIM], g_psumsq[DIM];
__device__ float  g_ta[3 * DIM], g_tc[3 * DIM];      // conv BN scale/shift
__device__ float  g_peA[DIM], g_peC[DIM];            // path-encoder BN scale/shift
__device__ float  g_combB[DIM];                      // pe_src_b + pe_tgt_b
__device__ float  g_cs[128 * TOPN];
__device__ int    g_ci[128 * TOPN];

// ---------------- small utility kernels ------------------------------------
__global__ void k_reset() {
    int t = blockIdx.x * blockDim.x + threadIdx.x;
    if (t < NSRC) g_cnt[t] = 0;
    if (t < 3 * DIM) { g_tsum[t] = 0.0; g_tsumsq[t] = 0.0; }
    if (t < DIM) { g_psum[t] = 0.0; g_psumsq[t] = 0.0; }
}

__global__ void k_hist(const int* __restrict__ sid) {
    int e = blockIdx.x * blockDim.x + threadIdx.x;
    if (e < NEDGE) atomicAdd(&g_cnt[sid[e]], 1);
}

// exclusive scan over 10000 counts; one block of 1024 threads, 10 items each
__global__ void k_scan() {
    __shared__ int s[1024];
    int t = threadIdx.x;
    int base = t * 10;
    int loc[10];
    int acc = 0;
#pragma unroll
    for (int j = 0; j < 10; j++) {
        int idx = base + j;
        int v = (idx < NSRC) ? g_cnt[idx] : 0;
        loc[j] = acc; acc += v;
    }
    s[t] = acc;
    __syncthreads();
    for (int off = 1; off < 1024; off <<= 1) {
        int v = (t >= off) ? s[t - off] : 0;
        __syncthreads();
        s[t] += v;
        __syncthreads();
    }
    int pre = (t > 0) ? s[t - 1] : 0;
#pragma unroll
    for (int j = 0; j < 10; j++) {
        int idx = base + j;
        if (idx < NSRC) { g_off[idx] = pre + loc[j]; g_cur[idx] = pre + loc[j]; }
    }
    if (t == 0) g_off[NSRC] = NEDGE;
}

__global__ void k_scatter(const int* __restrict__ sid) {
    int e = blockIdx.x * blockDim.x + threadIdx.x;
    if (e < NEDGE) {
        int p = atomicAdd(&g_cur[sid[e]], 1);
        g_order[p] = e;
    }
}

// one warp per node: sum relu(path_feats[row]) over the node's edge list
__global__ void k_agg(const float* __restrict__ pf) {
    int w = (blockIdx.x * blockDim.x + threadIdx.x) >> 5;
    int lane = threadIdx.x & 31;
    if (w >= NSRC) return;
    float acc[8];
#pragma unroll
    for (int j = 0; j < 8; j++) acc[j] = 0.f;
    int s = g_off[w], e2 = g_off[w + 1];
    for (int p = s; p < e2; p++) {
        int row = g_order[p];
        const float* r = pf + (size_t)row * EDIM;
#pragma unroll
        for (int j = 0; j < 8; j++) {
            int c = lane + 32 * j;
            if (c < EDIM) {
                float v = __ldg(r + c);
                acc[j] += (v > 0.f) ? v : 0.f;
            }
        }
    }
#pragma unroll
    for (int j = 0; j < 8; j++) {
        int c = lane + 32 * j;
        if (c < EDIM) g_agg[(size_t)w * EDIM + c] = acc[j];
    }
}

// ---------------- generic 128x128 fp32 GEMM (N fixed = 128) ----------------
// MODE 0: C = A@W
// MODE 1: C = A@W + bias[col]
// MODE 2: C = A@W + bias[col] + add[row,col]
// MODE 3: C = A@W ; also accumulate per-col sum/sumsq into g_tsum[sidx*128+...]
// MODE 4: A(n,k) = relu(g_ta[k]*g_T[...] + g_tc[k]) (Z concat, K=384);
//         C = relu(A@W + bias)
// MODE 5: C = A@W + g_combB[col]
template <int MODE>
__global__ void __launch_bounds__(256)
gemm128(const float* __restrict__ A, int M, int K, int lda,
        const float* __restrict__ W,
        const float* __restrict__ bias,
        const float* __restrict__ add,
        float* __restrict__ C, int sidx) {
    __shared__ float sA[8][128];
    __shared__ float sW[8][128];
    __shared__ float sS[128], sQ[128];
    int tid = threadIdx.x;
    int row0 = blockIdx.x * 128;
    int tx = tid & 15, ty = tid >> 4;
    float acc[8][8];
#pragma unroll
    for (int i = 0; i < 8; i++)
#pragma unroll
        for (int j = 0; j < 8; j++) acc[i][j] = 0.f;

    int ar = tid >> 1;          // A-tile row 0..127
    int ac = (tid & 1) * 4;     // A-tile k-offset 0 or 4
    int wk = (tid * 4) >> 7;    // W-tile k 0..7
    int wc = (tid * 4) & 127;   // W-tile col

    for (int kk = 0; kk < K; kk += 8) {
        float4 av = make_float4(0.f, 0.f, 0.f, 0.f);
        int grow = row0 + ar;
        if (MODE == 4) {
            if (grow < M) {
#pragma unroll
                for (int j = 0; j < 4; j++) {
                    int k = kk + ac + j;
                    float v = 0.f;
                    if (k < K) {
                        float t = g_T[((size_t)((k >> 7) * NSRC + grow)) * DIM + (k & 127)];
                        v = g_ta[k] * t + g_tc[k];
                        v = (v > 0.f) ? v : 0.f;
                    }
                    ((float*)&av)[j] = v;
                }
            }
        } else {
            if (grow < M) {
                int k = kk + ac;
                if (k + 3 < K) {
                    av = *(const float4*)(A + (size_t)grow * lda + k);
                } else {
#pragma unroll
                    for (int j = 0; j < 4; j++) {
                        int kj = k + j;
                        ((float*)&av)[j] = (kj < K) ? A[(size_t)grow * lda + kj] : 0.f;
                    }
                }
            }
        }
        sA[ac + 0][ar] = av.x; sA[ac + 1][ar] = av.y;
        sA[ac + 2][ar] = av.z; sA[ac + 3][ar] = av.w;

        float4 wv = make_float4(0.f, 0.f, 0.f, 0.f);
        if (kk + wk < K) wv = *(const float4*)(W + (size_t)(kk + wk) * 128 + wc);
        *(float4*)&sW[wk][wc] = wv;
        __syncthreads();

#pragma unroll
        for (int k = 0; k < 8; k++) {
            float4 a0 = *(float4*)&sA[k][ty * 8];
            float4 a1 = *(float4*)&sA[k][ty * 8 + 4];
            float4 b0 = *(float4*)&sW[k][tx * 8];
            float4 b1 = *(float4*)&sW[k][tx * 8 + 4];
            float ra[8] = {a0.x, a0.y, a0.z, a0.w, a1.x, a1.y, a1.z, a1.w};
            float rb[8] = {b0.x, b0.y, b0.z, b0.w, b1.x, b1.y, b1.z, b1.w};
#pragma unroll
            for (int i = 0; i < 8; i++)
#pragma unroll
                for (int j = 0; j < 8; j++) acc[i][j] += ra[i] * rb[j];
        }
        __syncthreads();
    }

    float ps[8], pq[8];
    if (MODE == 3) {
#pragma unroll
        for (int j = 0; j < 8; j++) { ps[j] = 0.f; pq[j] = 0.f; }
    }
#pragma unroll
    for (int i = 0; i < 8; i++) {
        int row = row0 + ty * 8 + i;
        if (row < M) {
#pragma unroll
            for (int j = 0; j < 8; j++) {
                int col = tx * 8 + j;
                float v = acc[i][j];
                if (MODE == 1) v += bias[col];
                if (MODE == 2) v += bias[col] + add[(size_t)row * DIM + col];
                if (MODE == 4) { v += bias[col]; v = (v > 0.f) ? v : 0.f; }
                if (MODE == 5) v += g_combB[col];
                C[(size_t)row * DIM + col] = v;
                if (MODE == 3) { ps[j] += v; pq[j] += v * v; }
            }
        }
    }
    if (MODE == 3) {
        if (tid < 128) { sS[tid] = 0.f; sQ[tid] = 0.f; }
        __syncthreads();
#pragma unroll
        for (int j = 0; j < 8; j++) {
            atomicAdd(&sS[tx * 8 + j], ps[j]);
            atomicAdd(&sQ[tx * 8 + j], pq[j]);
        }
        __syncthreads();
        if (tid < 128) {
            atomicAdd(&g_tsum[sidx * DIM + tid], (double)sS[tid]);
            atomicAdd(&g_tsumsq[sidx * DIM + tid], (double)sQ[tid]);
        }
    }
}

// ---------------- BN coefficient finalization -------------------------------
__global__ void k_coef1(const float* __restrict__ bng, const float* __restrict__ bnb,
                        const float* __restrict__ psb, const float* __restrict__ ptb) {
    int t = blockIdx.x * blockDim.x + threadIdx.x;
    if (t < 3 * DIM) {
        double mean = g_tsum[t] / NSRC;
        double var = g_tsumsq[t] / NSRC - mean * mean;
        float a = bng[t] * rsqrtf((float)var + BN_EPS);
        g_ta[t] = a;
        g_tc[t] = bnb[t] - a * (float)mean;
    }
    if (t < DIM) g_combB[t] = psb[t] + ptb[t];
}

__global__ void k_coef2(const float* __restrict__ peg, const float* __restrict__ peb) {
    int t = threadIdx.x;
    double mean = g_psum[t] / NEDGE;
    double var = g_psumsq[t] / NEDGE - mean * mean;
    float a = peg[t] * rsqrtf((float)var + BN_EPS);
    g_peA[t] = a;
    g_peC[t] = peb[t] - a * (float)mean;
}

// ---------------- path-encoder BN stats over y = xg + srcterm[sid] ----------
__global__ void k_pestats(const int* __restrict__ sid) {
    int c = threadIdx.x;            // 128 threads = columns
    int base = blockIdx.x * 256;    // 256 edges per block
    float s = 0.f, q = 0.f;
    for (int r = 0; r < 256; r++) {
        int e = base + r;
        float y = g_xg[(size_t)e * DIM + c] + g_srcterm[(size_t)sid[e] * DIM + c];
        s += y; q += y * y;
    }
    atomicAdd(&g_psum[c], (double)s);
    atomicAdd(&g_psumsq[c], (double)q);
}

// ---------------- scores: warp per edge group --------------------------------
__global__ void k_scores(const int* __restrict__ sid, const float* __restrict__ sw) {
    int w = (blockIdx.x * blockDim.x + threadIdx.x) >> 5;
    int lane = threadIdx.x & 31;
    int e0 = w * 64;
    float a[4], c4[4], wv[4];
#pragma unroll
    for (int j = 0; j < 4; j++) {
        int cc = lane + 32 * j;
        a[j] = g_peA[cc]; c4[j] = g_peC[cc]; wv[j] = sw[cc];
    }
    for (int e = e0; e < e0 + 64; e++) {
        const float* xr = g_xg + (size_t)e * DIM;
        const float* st = g_srcterm + (size_t)sid[e] * DIM;
        float p = 0.f;
#pragma unroll
        for (int j = 0; j < 4; j++) {
            int cc = lane + 32 * j;
            float y = xr[cc] + st[cc];
            float v = a[j] * y + c4[j];
            v = (v > 0.f) ? v : 0.f;
            p += v * wv[j];
        }
#pragma unroll
        for (int o = 16; o; o >>= 1) p += __shfl_xor_sync(0xffffffffu, p, o);
        if (lane == 0) g_scores[e] = p;
    }
}

// ---------------- top-k ------------------------------------------------------
__device__ __forceinline__ bool kbetter(float s1, int i1, float s2, int i2) {
    return (s1 > s2) || (s1 == s2 && i1 < i2);
}
__device__ __forceinline__ void top_insert(float* bs, int* bi, float v, int e) {
    if (!kbetter(v, e, bs[TOPN - 1], bi[TOPN - 1])) return;
    int p = TOPN - 1;
    while (p > 0 && kbetter(v, e, bs[p - 1], bi[p - 1])) {
        bs[p] = bs[p - 1]; bi[p] = bi[p - 1]; p--;
    }
    bs[p] = v; bi[p] = e;
}

__global__ void k_top_a() {
    float bs[TOPN]; int bi[TOPN];
#pragma unroll
    for (int j = 0; j < TOPN; j++) { bs[j] = -1e30f; bi[j] = 0x7fffffff; }
    int t = blockIdx.x * 256 + threadIdx.x;
    for (int e = t; e < NEDGE; e += 128 * 256) {
        top_insert(bs, bi, g_scores[e], e);
    }
    __shared__ float ss[256 * TOPN];
    __shared__ int si[256 * TOPN];
#pragma unroll
    for (int j = 0; j < TOPN; j++) {
        ss[threadIdx.x * TOPN + j] = bs[j];
        si[threadIdx.x * TOPN + j] = bi[j];
    }
    __syncthreads();
    if (threadIdx.x == 0) {
        float cs[TOPN]; int ci[TOPN];
#pragma unroll
        for (int j = 0; j < TOPN; j++) { cs[j] = -1e30f; ci[j] = 0x7fffffff; }
        for (int k = 0; k < 256 * TOPN; k++) top_insert(cs, ci, ss[k], si[k]);
        for (int j = 0; j < TOPN; j++) {
            g_cs[blockIdx.x * TOPN + j] = cs[j];
            g_ci[blockIdx.x * TOPN + j] = ci[j];
        }
    }
}

__global__ void k_top_b(float* __restrict__ out) {
    if (threadIdx.x == 0) {
        float cs[TOPN]; int ci[TOPN];
#pragma unroll
        for (int j = 0; j < TOPN; j++) { cs[j] = -1e30f; ci[j] = 0x7fffffff; }
        for (int k = 0; k < 128 * TOPN; k++) top_insert(cs, ci, g_cs[k], g_ci[k]);
        for (int j = 0; j < TOPN; j++) {
            out[(size_t)NSRC * DIM + j] = cs[j];
            out[(size_t)NSRC * DIM + TOPN + j] = (float)ci[j];
        }
    }
}

// ---------------- host entry -------------------------------------------------
extern "C" void kernel_launch(void* const* d_in, const int* in_sizes, int n_in,
                              void* d_out, int out_size) {
    // Dict order: src_ids is input 2 (320000 elems); signature order puts it last.
    bool dictorder = (in_sizes[2] == NEDGE);
    const float* paths = (const float*)d_in[0];
    const float* pf    = (const float*)d_in[1];
    const int*   sid   = (const int*)d_in[dictorder ? 2 : 19];
    int b = dictorder ? 3 : 2;
    const float* cew = (const float*)d_in[b + 0];
    const float* ceb = (const float*)d_in[b + 1];
    const float* w1  = (const float*)d_in[b + 2];
    const float* bng = (const float*)d_in[b + 3];
    const float* bnb = (const float*)d_in[b + 4];
    const float* w2  = (const float*)d_in[b + 5];
    const float* l1W = (const float*)d_in[b + 6];
    const float* l1b = (const float*)d_in[b + 7];
    const float* l2W = (const float*)d_in[b + 8];
    const float* l2b = (const float*)d_in[b + 9];
    const float* psW = (const float*)d_in[b + 10];
    const float* ptW = (const float*)d_in[b + 12];
    const float* psb = (const float*)d_in[b + 11];
    const float* ptb = (const float*)d_in[b + 13];
    const float* peg = (const float*)d_in[b + 14];
    const float* peb = (const float*)d_in[b + 15];
    const float* sw  = (const float*)d_in[b + 16];
    float* out = (float*)d_out;

    void *p_agg, *p_xg, *p_srcterm, *p_H, *p_T, *p_h2, *p_Wc;
    cudaGetSymbolAddress(&p_agg, g_agg);
    cudaGetSymbolAddress(&p_xg, g_xg);
    cudaGetSymbolAddress(&p_srcterm, g_srcterm);
    cudaGetSymbolAddress(&p_H, g_H);
    cudaGetSymbolAddress(&p_T, g_T);
    cudaGetSymbolAddress(&p_h2, g_h2);
    cudaGetSymbolAddress(&p_Wc, g_Wc);
    float* agg = (float*)p_agg;
    float* xg = (float*)p_xg;
    float* srcterm = (float*)p_srcterm;
    float* H = (float*)p_H;
    float* T = (float*)p_T;
    float* h2 = (float*)p_h2;
    float* Wc = (float*)p_Wc;

    const int NODE_BLKS = (NSRC + 127) / 128;   // 79

    k_reset<<<40, 256>>>();
    k_hist<<<(NEDGE + 255) / 256, 256>>>(sid);
    k_scan<<<1, 1024>>>();
    k_scatter<<<(NEDGE + 255) / 256, 256>>>(sid);
    k_agg<<<(NSRC * 32 + 255) / 256, 256>>>(pf);

    // fold conv_W2 into lin1: Wc_i = W2_i @ L1_i
    for (int i = 0; i < 3; i++)
        gemm128<0><<<1, 256>>>(w2 + (size_t)i * DIM * DIM, DIM, DIM, DIM,
                               l1W + (size_t)i * DIM * DIM, nullptr, nullptr,
                               Wc + (size_t)i * DIM * DIM, 0);

    // H_i = paths + agg @ We_i + b_i
    for (int i = 0; i < 3; i++)
        gemm128<2><<<NODE_BLKS, 256>>>(agg, NSRC, EDIM, EDIM,
                                       cew + (size_t)i * EDIM * DIM,
                                       ceb + (size_t)i * DIM, paths,
                                       H + (size_t)i * NSRC * DIM, 0);
    // T_i = H_i @ W1_i (+ BN stats)
    for (int i = 0; i < 3; i++)
        gemm128<3><<<NODE_BLKS, 256>>>(H + (size_t)i * NSRC * DIM, NSRC, DIM, DIM,
                                       w1 + (size_t)i * DIM * DIM, nullptr, nullptr,
                                       T + (size_t)i * NSRC * DIM, i);
    k_coef1<<<2, 256>>>(bng, bnb, psb, ptb);

    // h2 = relu(concat(relu(BN(T_i))) @ Wc + lin1_b)
    gemm128<4><<<NODE_BLKS, 256>>>(nullptr, NSRC, 3 * DIM, 0, Wc, l1b, nullptr, h2, 0);
    // node_emb -> d_out
    gemm128<1><<<NODE_BLKS, 256>>>(h2, NSRC, DIM, DIM, l2W, l2b, nullptr, out, 0);
    // srcterm = node_emb @ pe_src_W + (pe_src_b + pe_tgt_b)
    gemm128<5><<<NODE_BLKS, 256>>>(out, NSRC, DIM, DIM, psW, nullptr, nullptr, srcterm, 0);

    // big edge GEMM: xg = path_feats @ pe_tgt_W
    gemm128<0><<<NEDGE / 128, 256>>>(pf, NEDGE, EDIM, EDIM, ptW, nullptr, nullptr, xg, 0);

    // path-encoder BN stats, coefficients, scores, top-k
    k_pestats<<<NEDGE / 256, 128>>>(sid);
    k_coef2<<<1, 128>>>(peg, peb);
    k_scores<<<NEDGE / 512, 256>>>(sid, sw);
    k_top_a<<<128, 256>>>();
    k_top_b<<<1, 32>>>(out);
}

// round 5
// speedup vs baseline: 1.3838x; 1.3838x over previous
#include <cuda_runtime.h>
#include <cuda_bf16.h>
#include <math.h>
#include <stdint.h>

#define NSRC 10000
#define NEDGE 320000
#define DIM 128
#define EDIM 236
#define TOPN 6
#define BN_EPS 1e-5f

// ---------------- scratch (device globals; no allocation allowed) ----------
__device__ float  g_agg[(size_t)NSRC * EDIM];
__device__ float  g_xg[(size_t)NEDGE * DIM];
__device__ float  g_srcterm[(size_t)NSRC * DIM];
__device__ float  g_H[(size_t)3 * NSRC * DIM];
__device__ float  g_T[(size_t)3 * NSRC * DIM];
__device__ float  g_h2[(size_t)NSRC * DIM];
__device__ float  g_Wc[3 * DIM * DIM];
__device__ float  g_scores[NEDGE];
__device__ int    g_cnt[NSRC];
__device__ int    g_off[NSRC + 1];
__device__ int    g_cur[NSRC];
__device__ int    g_order[NEDGE];
__device__ double g_tsum[3 * DIM], g_tsumsq[3 * DIM];
__device__ double g_psum[DIM], g_psumsq[DIM];
__device__ float  g_ta[3 * DIM], g_tc[3 * DIM];
__device__ float  g_peA[DIM], g_peC[DIM];
__device__ float  g_combB[DIM];
__device__ float  g_cs[128 * TOPN];
__device__ int    g_ci[128 * TOPN];

// ---------------- small utility kernels ------------------------------------
__global__ void k_reset() {
    int t = blockIdx.x * blockDim.x + threadIdx.x;
    if (t < NSRC) g_cnt[t] = 0;
    if (t < 3 * DIM) { g_tsum[t] = 0.0; g_tsumsq[t] = 0.0; }
    if (t < DIM) { g_psum[t] = 0.0; g_psumsq[t] = 0.0; }
}

__global__ void k_hist(const int* __restrict__ sid) {
    int e = blockIdx.x * blockDim.x + threadIdx.x;
    if (e < NEDGE) atomicAdd(&g_cnt[sid[e]], 1);
}

__global__ void k_scan() {
    __shared__ int s[1024];
    int t = threadIdx.x;
    int base = t * 10;
    int loc[10];
    int acc = 0;
#pragma unroll
    for (int j = 0; j < 10; j++) {
        int idx = base + j;
        int v = (idx < NSRC) ? g_cnt[idx] : 0;
        loc[j] = acc; acc += v;
    }
    s[t] = acc;
    __syncthreads();
    for (int off = 1; off < 1024; off <<= 1) {
        int v = (t >= off) ? s[t - off] : 0;
        __syncthreads();
        s[t] += v;
        __syncthreads();
    }
    int pre = (t > 0) ? s[t - 1] : 0;
#pragma unroll
    for (int j = 0; j < 10; j++) {
        int idx = base + j;
        if (idx < NSRC) { g_off[idx] = pre + loc[j]; g_cur[idx] = pre + loc[j]; }
    }
    if (t == 0) g_off[NSRC] = NEDGE;
}

__global__ void k_scatter(const int* __restrict__ sid) {
    int e = blockIdx.x * blockDim.x + threadIdx.x;
    if (e < NEDGE) {
        int p = atomicAdd(&g_cur[sid[e]], 1);
        g_order[p] = e;
    }
}

__global__ void k_agg(const float* __restrict__ pf) {
    int w = (blockIdx.x * blockDim.x + threadIdx.x) >> 5;
    int lane = threadIdx.x & 31;
    if (w >= NSRC) return;
    float acc[8];
#pragma unroll
    for (int j = 0; j < 8; j++) acc[j] = 0.f;
    int s = g_off[w], e2 = g_off[w + 1];
    for (int p = s; p < e2; p++) {
        int row = g_order[p];
        const float* r = pf + (size_t)row * EDIM;
#pragma unroll
        for (int j = 0; j < 8; j++) {
            int c = lane + 32 * j;
            if (c < EDIM) {
                float v = __ldg(r + c);
                acc[j] += (v > 0.f) ? v : 0.f;
            }
        }
    }
#pragma unroll
    for (int j = 0; j < 8; j++) {
        int c = lane + 32 * j;
        if (c < EDIM) g_agg[(size_t)w * EDIM + c] = acc[j];
    }
}

// ---------------- generic 128x128 fp32 GEMM, batched over blockIdx.y --------
template <int MODE>
__global__ void __launch_bounds__(256)
gemm128(const float* __restrict__ A, int M, int K, int lda, long astr,
        const float* __restrict__ W, long wstr,
        const float* __restrict__ bias, int bstr,
        const float* __restrict__ add,
        float* __restrict__ C, long cstr) {
    int bz = blockIdx.y;
    if (A) A += (size_t)bz * astr;
    W += (size_t)bz * wstr;
    if (bias) bias += (size_t)bz * bstr;
    C += (size_t)bz * cstr;
    int sidx = bz;

    __shared__ float sA[8][128];
    __shared__ float sW[8][128];
    __shared__ float sS[128], sQ[128];
    int tid = threadIdx.x;
    int row0 = blockIdx.x * 128;
    int tx = tid & 15, ty = tid >> 4;
    float acc[8][8];
#pragma unroll
    for (int i = 0; i < 8; i++)
#pragma unroll
        for (int j = 0; j < 8; j++) acc[i][j] = 0.f;

    int ar = tid >> 1;
    int ac = (tid & 1) * 4;
    int wk = (tid * 4) >> 7;
    int wc = (tid * 4) & 127;

    for (int kk = 0; kk < K; kk += 8) {
        float4 av = make_float4(0.f, 0.f, 0.f, 0.f);
        int grow = row0 + ar;
        if (MODE == 4) {
            if (grow < M) {
#pragma unroll
                for (int j = 0; j < 4; j++) {
                    int k = kk + ac + j;
                    float v = 0.f;
                    if (k < K) {
                        float t = g_T[((size_t)((k >> 7) * NSRC + grow)) * DIM + (k & 127)];
                        v = g_ta[k] * t + g_tc[k];
                        v = (v > 0.f) ? v : 0.f;
                    }
                    ((float*)&av)[j] = v;
                }
            }
        } else {
            if (grow < M) {
                int k = kk + ac;
                if (k + 3 < K) {
                    av = *(const float4*)(A + (size_t)grow * lda + k);
                } else {
#pragma unroll
                    for (int j = 0; j < 4; j++) {
                        int kj = k + j;
                        ((float*)&av)[j] = (kj < K) ? A[(size_t)grow * lda + kj] : 0.f;
                    }
                }
            }
        }
        sA[ac + 0][ar] = av.x; sA[ac + 1][ar] = av.y;
        sA[ac + 2][ar] = av.z; sA[ac + 3][ar] = av.w;

        float4 wv = make_float4(0.f, 0.f, 0.f, 0.f);
        if (kk + wk < K) wv = *(const float4*)(W + (size_t)(kk + wk) * 128 + wc);
        *(float4*)&sW[wk][wc] = wv;
        __syncthreads();

#pragma unroll
        for (int k = 0; k < 8; k++) {
            float4 a0 = *(float4*)&sA[k][ty * 8];
            float4 a1 = *(float4*)&sA[k][ty * 8 + 4];
            float4 b0 = *(float4*)&sW[k][tx * 8];
            float4 b1 = *(float4*)&sW[k][tx * 8 + 4];
            float ra[8] = {a0.x, a0.y, a0.z, a0.w, a1.x, a1.y, a1.z, a1.w};
            float rb[8] = {b0.x, b0.y, b0.z, b0.w, b1.x, b1.y, b1.z, b1.w};
#pragma unroll
            for (int i = 0; i < 8; i++)
#pragma unroll
                for (int j = 0; j < 8; j++) acc[i][j] += ra[i] * rb[j];
        }
        __syncthreads();
    }

    float ps[8], pq[8];
    if (MODE == 3) {
#pragma unroll
        for (int j = 0; j < 8; j++) { ps[j] = 0.f; pq[j] = 0.f; }
    }
#pragma unroll
    for (int i = 0; i < 8; i++) {
        int row = row0 + ty * 8 + i;
        if (row < M) {
#pragma unroll
            for (int j = 0; j < 8; j++) {
                int col = tx * 8 + j;
                float v = acc[i][j];
                if (MODE == 1) v += bias[col];
                if (MODE == 2) v += bias[col] + add[(size_t)row * DIM + col];
                if (MODE == 4) { v += bias[col]; v = (v > 0.f) ? v : 0.f; }
                if (MODE == 5) v += g_combB[col];
                C[(size_t)row * DIM + col] = v;
                if (MODE == 3) { ps[j] += v; pq[j] += v * v; }
            }
        }
    }
    if (MODE == 3) {
        if (tid < 128) { sS[tid] = 0.f; sQ[tid] = 0.f; }
        __syncthreads();
#pragma unroll
        for (int j = 0; j < 8; j++) {
            atomicAdd(&sS[tx * 8 + j], ps[j]);
            atomicAdd(&sQ[tx * 8 + j], pq[j]);
        }
        __syncthreads();
        if (tid < 128) {
            atomicAdd(&g_tsum[sidx * DIM + tid], (double)sS[tid]);
            atomicAdd(&g_tsumsq[sidx * DIM + tid], (double)sQ[tid]);
        }
    }
}

// =================== HMMA split-bf16 edge GEMM ==============================
// xg[320000,128] = path_feats[320000,236] @ pe_tgt_W[236,128]
// Split: Ah=bf16(a), Al=bf16(a-Ah); C = Ah*Bh + Ah*Bl + Al*Bh (fp32 accum).
// mma.sync.m16n8k16 bf16 is a BASE sm_80+ feature (works with sm_103 ptxas).
#define LDE 66                       // padded leading dim (elems); 132B rows = 33 words
#define SZ_T (128 * LDE * 2)         // 16896 bytes per tile buffer
#define EG_SMEM (4 * SZ_T)           // Ah, Al, Bh, Bl

__device__ __forceinline__ void mma16816(float* c, const uint32_t* a, const uint32_t* b) {
    asm volatile(
        "mma.sync.aligned.m16n8k16.row.col.f32.bf16.bf16.f32 "
        "{%0,%1,%2,%3}, {%4,%5,%6,%7}, {%8,%9}, {%0,%1,%2,%3};"
        : "+f"(c[0]), "+f"(c[1]), "+f"(c[2]), "+f"(c[3])
        : "r"(a[0]), "r"(a[1]), "r"(a[2]), "r"(a[3]), "r"(b[0]), "r"(b[1]));
}

__global__ void __launch_bounds__(256, 1)
k_edge_gemm(const float* __restrict__ pf, const float* __restrict__ ptW) {
    extern __shared__ char smem[];
    char* smAh = smem;
    char* smAl = smem + SZ_T;
    char* smBh = smem + 2 * SZ_T;
    char* smBl = smem + 3 * SZ_T;
    int tid = threadIdx.x, wid = tid >> 5, lane = tid & 31;
    int g = lane >> 2, tg = lane & 3;
    int warpM = wid & 1, warpN = wid >> 1;   // 2 x 4 warp grid; warp tile 64x32
    int row0 = blockIdx.x * 128;

    float acc[4][4][4];
#pragma unroll
    for (int mt = 0; mt < 4; mt++)
#pragma unroll
        for (int nt = 0; nt < 4; nt++)
#pragma unroll
            for (int j = 0; j < 4; j++) acc[mt][nt][j] = 0.f;

    for (int kk = 0; kk < 256; kk += 64) {
        // A chunk: 128 rows x 64 k  -> hi/lo bf16 smem [r][c], LDE-padded
#pragma unroll
        for (int it = 0; it < 32; it++) {
            int idx = tid + it * 256;
            int r = idx >> 6, c = idx & 63;
            int k = kk + c;
            float a = (k < EDIM) ? __ldg(pf + (size_t)(row0 + r) * EDIM + k) : 0.f;
            __nv_bfloat16 h = __float2bfloat16(a);
            __nv_bfloat16 l = __float2bfloat16(a - __bfloat162float(h));
            int off = (r * LDE + c) * 2;
            *(__nv_bfloat16*)(smAh + off) = h;
            *(__nv_bfloat16*)(smAl + off) = l;
        }
        // B chunk: 64 k x 128 n -> stored transposed [n][c] (k contiguous)
#pragma unroll
        for (int it = 0; it < 32; it++) {
            int idx = tid + it * 256;
            int c = idx >> 7, n = idx & 127;
            int k = kk + c;
            float b = (k < EDIM) ? __ldg(ptW + (size_t)k * DIM + n) : 0.f;
            __nv_bfloat16 h = __float2bfloat16(b);
            __nv_bfloat16 l = __float2bfloat16(b - __bfloat162float(h));
            int off = (n * LDE + c) * 2;
            *(__nv_bfloat16*)(smBh + off) = h;
            *(__nv_bfloat16*)(smBl + off) = l;
        }
        __syncthreads();

#pragma unroll
        for (int ks = 0; ks < 4; ks++) {
            int k0 = ks * 16;
            uint32_t ah[4][4], al[4][4], bh[4][2], bl[4][2];
#pragma unroll
            for (int mt = 0; mt < 4; mt++) {
                int m = warpM * 64 + mt * 16;
                int o0 = ((m + g) * LDE + k0 + 2 * tg) * 2;
                int o1 = ((m + g + 8) * LDE + k0 + 2 * tg) * 2;
                ah[mt][0] = *(const uint32_t*)(smAh + o0);
                ah[mt][1] = *(const uint32_t*)(smAh + o1);
                ah[mt][2] = *(const uint32_t*)(smAh + o0 + 16);
                ah[mt][3] = *(const uint32_t*)(smAh + o1 + 16);
                al[mt][0] = *(const uint32_t*)(smAl + o0);
                al[mt][1] = *(const uint32_t*)(smAl + o1);
                al[mt][2] = *(const uint32_t*)(smAl + o0 + 16);
                al[mt][3] = *(const uint32_t*)(smAl + o1 + 16);
            }
#pragma unroll
            for (int nt = 0; nt < 4; nt++) {
                int n = warpN * 32 + nt * 8 + g;
                int o0 = (n * LDE + k0 + 2 * tg) * 2;
                bh[nt][0] = *(const uint32_t*)(smBh + o0);
                bh[nt][1] = *(const uint32_t*)(smBh + o0 + 16);
                bl[nt][0] = *(const uint32_t*)(smBl + o0);
                bl[nt][1] = *(const uint32_t*)(smBl + o0 + 16);
            }
#pragma unroll
            for (int mt = 0; mt < 4; mt++)
#pragma unroll
                for (int nt = 0; nt < 4; nt++) {
                    mma16816(acc[mt][nt], ah[mt], bh[nt]);
                    mma16816(acc[mt][nt], ah[mt], bl[nt]);
                    mma16816(acc[mt][nt], al[mt], bh[nt]);
                }
        }
        __syncthreads();
    }

    // epilogue: C[g][2tg],C[g][2tg+1] in c0,c1 ; rows +8 in c2,c3
#pragma unroll
    for (int mt = 0; mt < 4; mt++) {
        int r0 = row0 + warpM * 64 + mt * 16 + g;
#pragma unroll
        for (int nt = 0; nt < 4; nt++) {
            int n = warpN * 32 + nt * 8 + 2 * tg;
            float2 v0 = make_float2(acc[mt][nt][0], acc[mt][nt][1]);
            float2 v1 = make_float2(acc[mt][nt][2], acc[mt][nt][3]);
            *(float2*)(g_xg + (size_t)r0 * DIM + n) = v0;
            *(float2*)(g_xg + (size_t)(r0 + 8) * DIM + n) = v1;
        }
    }
}

// ---------------- BN coefficient finalization -------------------------------
__global__ void k_coef1(const float* __restrict__ bng, const float* __restrict__ bnb,
                        const float* __restrict__ psb, const float* __restrict__ ptb) {
    int t = blockIdx.x * blockDim.x + threadIdx.x;
    if (t < 3 * DIM) {
        double mean = g_tsum[t] / NSRC;
        double var = g_tsumsq[t] / NSRC - mean * mean;
        float a = bng[t] * rsqrtf((float)var + BN_EPS);
        g_ta[t] = a;
        g_tc[t] = bnb[t] - a * (float)mean;
    }
    if (t < DIM) g_combB[t] = psb[t] + ptb[t];
}

__global__ void k_coef2(const float* __restrict__ peg, const float* __restrict__ peb) {
    int t = threadIdx.x;
    double mean = g_psum[t] / NEDGE;
    double var = g_psumsq[t] / NEDGE - mean * mean;
    float a = peg[t] * rsqrtf((float)var + BN_EPS);
    g_peA[t] = a;
    g_peC[t] = peb[t] - a * (float)mean;
}

// ---------------- path-encoder BN stats over y = xg + srcterm[sid] ----------
__global__ void k_pestats(const int* __restrict__ sid) {
    int c = threadIdx.x;
    int base = blockIdx.x * 256;
    float s = 0.f, q = 0.f;
    for (int r = 0; r < 256; r++) {
        int e = base + r;
        float y = g_xg[(size_t)e * DIM + c] + g_srcterm[(size_t)sid[e] * DIM + c];
        s += y; q += y * y;
    }
    atomicAdd(&g_psum[c], (double)s);
    atomicAdd(&g_psumsq[c], (double)q);
}

// ---------------- scores -----------------------------------------------------
__global__ void k_scores(const int* __restrict__ sid, const float* __restrict__ sw) {
    int w = (blockIdx.x * blockDim.x + threadIdx.x) >> 5;
    int lane = threadIdx.x & 31;
    int e0 = w * 64;
    float a[4], c4[4], wv[4];
#pragma unroll
    for (int j = 0; j < 4; j++) {
        int cc = lane + 32 * j;
        a[j] = g_peA[cc]; c4[j] = g_peC[cc]; wv[j] = sw[cc];
    }
    for (int e = e0; e < e0 + 64; e++) {
        const float* xr = g_xg + (size_t)e * DIM;
        const float* st = g_srcterm + (size_t)sid[e] * DIM;
        float p = 0.f;
#pragma unroll
        for (int j = 0; j < 4; j++) {
            int cc = lane + 32 * j;
            float y = xr[cc] + st[cc];
            float v = a[j] * y + c4[j];
            v = (v > 0.f) ? v : 0.f;
            p += v * wv[j];
        }
#pragma unroll
        for (int o = 16; o; o >>= 1) p += __shfl_xor_sync(0xffffffffu, p, o);
        if (lane == 0) g_scores[e] = p;
    }
}

// ---------------- top-k ------------------------------------------------------
__device__ __forceinline__ bool kbetter(float s1, int i1, float s2, int i2) {
    return (s1 > s2) || (s1 == s2 && i1 < i2);
}
__device__ __forceinline__ void top_insert(float* bs, int* bi, float v, int e) {
    if (!kbetter(v, e, bs[TOPN - 1], bi[TOPN - 1])) return;
    int p = TOPN - 1;
    while (p > 0 && kbetter(v, e, bs[p - 1], bi[p - 1])) {
        bs[p] = bs[p - 1]; bi[p] = bi[p - 1]; p--;
    }
    bs[p] = v; bi[p] = e;
}

__global__ void k_top_a() {
    float bs[TOPN]; int bi[TOPN];
#pragma unroll
    for (int j = 0; j < TOPN; j++) { bs[j] = -1e30f; bi[j] = 0x7fffffff; }
    int t = blockIdx.x * 256 + threadIdx.x;
    for (int e = t; e < NEDGE; e += 128 * 256) {
        top_insert(bs, bi, g_scores[e], e);
    }
    __shared__ float ss[256 * TOPN];
    __shared__ int si[256 * TOPN];
#pragma unroll
    for (int j = 0; j < TOPN; j++) {
        ss[threadIdx.x * TOPN + j] = bs[j];
        si[threadIdx.x * TOPN + j] = bi[j];
    }
    __syncthreads();
    if (threadIdx.x == 0) {
        float cs[TOPN]; int ci[TOPN];
#pragma unroll
        for (int j = 0; j < TOPN; j++) { cs[j] = -1e30f; ci[j] = 0x7fffffff; }
        for (int k = 0; k < 256 * TOPN; k++) top_insert(cs, ci, ss[k], si[k]);
        for (int j = 0; j < TOPN; j++) {
            g_cs[blockIdx.x * TOPN + j] = cs[j];
            g_ci[blockIdx.x * TOPN + j] = ci[j];
        }
    }
}

__global__ void k_top_b(float* __restrict__ out) {
    if (threadIdx.x == 0) {
        float cs[TOPN]; int ci[TOPN];
#pragma unroll
        for (int j = 0; j < TOPN; j++) { cs[j] = -1e30f; ci[j] = 0x7fffffff; }
        for (int k = 0; k < 128 * TOPN; k++) top_insert(cs, ci, g_cs[k], g_ci[k]);
        for (int j = 0; j < TOPN; j++) {
            out[(size_t)NSRC * DIM + j] = cs[j];
            out[(size_t)NSRC * DIM + TOPN + j] = (float)ci[j];
        }
    }
}

// ---------------- host entry -------------------------------------------------
extern "C" void kernel_launch(void* const* d_in, const int* in_sizes, int n_in,
                              void* d_out, int out_size) {
    bool dictorder = (in_sizes[2] == NEDGE);
    const float* paths = (const float*)d_in[0];
    const float* pf    = (const float*)d_in[1];
    const int*   sid   = (const int*)d_in[dictorder ? 2 : 19];
    int b = dictorder ? 3 : 2;
    const float* cew = (const float*)d_in[b + 0];
    const float* ceb = (const float*)d_in[b + 1];
    const float* w1  = (const float*)d_in[b + 2];
    const float* bng = (const float*)d_in[b + 3];
    const float* bnb = (const float*)d_in[b + 4];
    const float* w2  = (const float*)d_in[b + 5];
    const float* l1W = (const float*)d_in[b + 6];
    const float* l1b = (const float*)d_in[b + 7];
    const float* l2W = (const float*)d_in[b + 8];
    const float* l2b = (const float*)d_in[b + 9];
    const float* psW = (const float*)d_in[b + 10];
    const float* psb = (const float*)d_in[b + 11];
    const float* ptW = (const float*)d_in[b + 12];
    const float* ptb = (const float*)d_in[b + 13];
    const float* peg = (const float*)d_in[b + 14];
    const float* peb = (const float*)d_in[b + 15];
    const float* sw  = (const float*)d_in[b + 16];
    float* out = (float*)d_out;

    void *p_agg, *p_Wc, *p_H, *p_T, *p_h2, *p_srcterm;
    cudaGetSymbolAddress(&p_agg, g_agg);
    cudaGetSymbolAddress(&p_Wc, g_Wc);
    cudaGetSymbolAddress(&p_H, g_H);
    cudaGetSymbolAddress(&p_T, g_T);
    cudaGetSymbolAddress(&p_h2, g_h2);
    cudaGetSymbolAddress(&p_srcterm, g_srcterm);
    float* agg = (float*)p_agg;
    float* Wc = (float*)p_Wc;
    float* H = (float*)p_H;
    float* T = (float*)p_T;
    float* h2 = (float*)p_h2;
    float* srcterm = (float*)p_srcterm;

    cudaFuncSetAttribute(k_edge_gemm, cudaFuncAttributeMaxDynamicSharedMemorySize, EG_SMEM);

    const int NODE_BLKS = (NSRC + 127) / 128;   // 79

    k_reset<<<40, 256>>>();
    k_hist<<<(NEDGE + 255) / 256, 256>>>(sid);
    k_scan<<<1, 1024>>>();
    k_scatter<<<(NEDGE + 255) / 256, 256>>>(sid);
    k_agg<<<(NSRC * 32 + 255) / 256, 256>>>(pf);

    // Wc_i = W2_i @ L1_i (batched over y)
    gemm128<0><<<dim3(1, 3), 256>>>(w2, DIM, DIM, DIM, (long)DIM * DIM,
                                    l1W, (long)DIM * DIM, nullptr, 0, nullptr,
                                    Wc, (long)DIM * DIM);
    // H_i = paths + agg @ We_i + b_i  (batched)
    gemm128<2><<<dim3(NODE_BLKS, 3), 256>>>(agg, NSRC, EDIM, EDIM, 0L,
                                            cew, (long)EDIM * DIM, ceb, DIM, paths,
                                            H, (long)NSRC * DIM);
    // T_i = H_i @ W1_i (+ BN stats)  (batched)
    gemm128<3><<<dim3(NODE_BLKS, 3), 256>>>(H, NSRC, DIM, DIM, (long)NSRC * DIM,
                                            w1, (long)DIM * DIM, nullptr, 0, nullptr,
                                            T, (long)NSRC * DIM);
    k_coef1<<<2, 256>>>(bng, bnb, psb, ptb);

    // h2 = relu(concat(relu(BN(T_i))) @ Wc + lin1_b)
    gemm128<4><<<dim3(NODE_BLKS, 1), 256>>>(nullptr, NSRC, 3 * DIM, 0, 0L,
                                            Wc, 0L, l1b, 0, nullptr, h2, 0L);
    // node_emb -> d_out
    gemm128<1><<<dim3(NODE_BLKS, 1), 256>>>(h2, NSRC, DIM, DIM, 0L,
                                            l2W, 0L, l2b, 0, nullptr, out, 0L);
    // srcterm = node_emb @ pe_src_W + (pe_src_b + pe_tgt_b)
    gemm128<5><<<dim3(NODE_BLKS, 1), 256>>>(out, NSRC, DIM, DIM, 0L,
                                            psW, 0L, nullptr, 0, nullptr, srcterm, 0L);

    // big edge GEMM on HMMA tensor cores (split-bf16): xg = path_feats @ pe_tgt_W
    k_edge_gemm<<<NEDGE / 128, 256, EG_SMEM>>>(pf, ptW);

    k_pestats<<<NEDGE / 256, 128>>>(sid);
    k_coef2<<<1, 128>>>(peg, peb);
    k_scores<<<NEDGE / 512, 256>>>(sid, sw);
    k_top_a<<<128, 256>>>();
    k_top_b<<<1, 32>>>(out);
}

// round 6
// speedup vs baseline: 1.6426x; 1.1870x over previous
#include <cuda_runtime.h>
#include <cuda_bf16.h>
#include <math.h>
#include <stdint.h>

#define NSRC 10000
#define NEDGE 320000
#define DIM 128
#define EDIM 236
#define TOPN 6
#define BN_EPS 1e-5f

// ---------------- scratch (device globals; no allocation allowed) ----------
__device__ float  g_agg[(size_t)NSRC * EDIM];
__device__ float  g_xg[(size_t)NEDGE * DIM];         // holds y = xg + srcterm[sid]
__device__ float  g_srcterm[(size_t)NSRC * DIM];
__device__ float  g_H[(size_t)3 * NSRC * DIM];
__device__ float  g_T[(size_t)3 * NSRC * DIM];
__device__ float  g_h2[(size_t)NSRC * DIM];
__device__ float  g_Wc[3 * DIM * DIM];
__device__ float  g_scores[NEDGE];
__device__ int    g_cnt[NSRC];
__device__ int    g_off[NSRC + 1];
__device__ int    g_cur[NSRC];
__device__ int    g_order[NEDGE];
__device__ double g_tsum[3 * DIM], g_tsumsq[3 * DIM];
__device__ double g_psumB[32 * DIM], g_psumsqB[32 * DIM];   // bucketed pe-BN stats
__device__ float  g_ta[3 * DIM], g_tc[3 * DIM];
__device__ float  g_peA[DIM], g_peC[DIM];
__device__ float  g_combB[DIM];
__device__ float  g_cs[128 * TOPN];
__device__ int    g_ci[128 * TOPN];
__device__ __nv_bfloat16 g_Bh[128 * 256];            // pe_tgt_W^T split-bf16 hi
__device__ __nv_bfloat16 g_Bl[128 * 256];            // lo

// ---------------- small utility kernels ------------------------------------
__global__ void k_reset() {
    int t = blockIdx.x * blockDim.x + threadIdx.x;
    if (t < NSRC) g_cnt[t] = 0;
    if (t < 3 * DIM) { g_tsum[t] = 0.0; g_tsumsq[t] = 0.0; }
    if (t < 32 * DIM) { g_psumB[t] = 0.0; g_psumsqB[t] = 0.0; }
}

__global__ void k_hist(const int* __restrict__ sid) {
    int e = blockIdx.x * blockDim.x + threadIdx.x;
    if (e < NEDGE) atomicAdd(&g_cnt[sid[e]], 1);
}

__global__ void k_scan() {
    __shared__ int s[1024];
    int t = threadIdx.x;
    int base = t * 10;
    int loc[10];
    int acc = 0;
#pragma unroll
    for (int j = 0; j < 10; j++) {
        int idx = base + j;
        int v = (idx < NSRC) ? g_cnt[idx] : 0;
        loc[j] = acc; acc += v;
    }
    s[t] = acc;
    __syncthreads();
    for (int off = 1; off < 1024; off <<= 1) {
        int v = (t >= off) ? s[t - off] : 0;
        __syncthreads();
        s[t] += v;
        __syncthreads();
    }
    int pre = (t > 0) ? s[t - 1] : 0;
#pragma unroll
    for (int j = 0; j < 10; j++) {
        int idx = base + j;
        if (idx < NSRC) { g_off[idx] = pre + loc[j]; g_cur[idx] = pre + loc[j]; }
    }
    if (t == 0) g_off[NSRC] = NEDGE;
}

__global__ void k_scatter(const int* __restrict__ sid) {
    int e = blockIdx.x * blockDim.x + threadIdx.x;
    if (e < NEDGE) {
        int p = atomicAdd(&g_cur[sid[e]], 1);
        g_order[p] = e;
    }
}

// B prep: split pe_tgt_W[236,128] into bf16 hi/lo, transposed to [n][256]
__global__ void k_prepB(const float* __restrict__ ptW) {
    int idx = blockIdx.x * 256 + threadIdx.x;
    if (idx >= 128 * 256) return;
    int k = idx >> 7, n = idx & 127;   // consecutive tid -> consecutive n (coalesced read)
    float b = (k < EDIM) ? ptW[(size_t)k * DIM + n] : 0.f;
    __nv_bfloat16 h = __float2bfloat16(b);
    __nv_bfloat16 l = __float2bfloat16(b - __bfloat162float(h));
    g_Bh[n * 256 + k] = h;
    g_Bl[n * 256 + k] = l;
}

// one warp per node, float4 lanes (236 = 59 float4 exactly)
__global__ void k_agg(const float* __restrict__ pf) {
    int w = (blockIdx.x * blockDim.x + threadIdx.x) >> 5;
    int lane = threadIdx.x & 31;
    if (w >= NSRC) return;
    float4 a0 = make_float4(0.f, 0.f, 0.f, 0.f);
    float4 a1 = make_float4(0.f, 0.f, 0.f, 0.f);
    int s = g_off[w], e2 = g_off[w + 1];
    for (int p = s; p < e2; p++) {
        const float4* r = (const float4*)(pf + (size_t)g_order[p] * EDIM);
        float4 v = __ldg(r + lane);
        a0.x += fmaxf(v.x, 0.f); a0.y += fmaxf(v.y, 0.f);
        a0.z += fmaxf(v.z, 0.f); a0.w += fmaxf(v.w, 0.f);
        if (lane < 27) {
            float4 v2 = __ldg(r + 32 + lane);
            a1.x += fmaxf(v2.x, 0.f); a1.y += fmaxf(v2.y, 0.f);
            a1.z += fmaxf(v2.z, 0.f); a1.w += fmaxf(v2.w, 0.f);
        }
    }
    float4* outp = (float4*)(g_agg + (size_t)w * EDIM);
    outp[lane] = a0;
    if (lane < 27) outp[32 + lane] = a1;
}

// ---------------- generic 128x128 fp32 GEMM, batched over blockIdx.y --------
template <int MODE>
__global__ void __launch_bounds__(256)
gemm128(const float* __restrict__ A, int M, int K, int lda, long astr,
        const float* __restrict__ W, long wstr,
        const float* __restrict__ bias, int bstr,
        const float* __restrict__ add,
        float* __restrict__ C, long cstr) {
    int bz = blockIdx.y;
    if (A) A += (size_t)bz * astr;
    W += (size_t)bz * wstr;
    if (bias) bias += (size_t)bz * bstr;
    C += (size_t)bz * cstr;
    int sidx = bz;

    __shared__ float sA[8][128];
    __shared__ float sW[8][128];
    __shared__ float sS[128], sQ[128];
    int tid = threadIdx.x;
    int row0 = blockIdx.x * 128;
    int tx = tid & 15, ty = tid >> 4;
    float acc[8][8];
#pragma unroll
    for (int i = 0; i < 8; i++)
#pragma unroll
        for (int j = 0; j < 8; j++) acc[i][j] = 0.f;

    int ar = tid >> 1;
    int ac = (tid & 1) * 4;
    int wk = (tid * 4) >> 7;
    int wc = (tid * 4) & 127;

    for (int kk = 0; kk < K; kk += 8) {
        float4 av = make_float4(0.f, 0.f, 0.f, 0.f);
        int grow = row0 + ar;
        if (MODE == 4) {
            if (grow < M) {
#pragma unroll
                for (int j = 0; j < 4; j++) {
                    int k = kk + ac + j;
                    float v = 0.f;
                    if (k < K) {
                        float t = g_T[((size_t)((k >> 7) * NSRC + grow)) * DIM + (k & 127)];
                        v = g_ta[k] * t + g_tc[k];
                        v = (v > 0.f) ? v : 0.f;
                    }
                    ((float*)&av)[j] = v;
                }
            }
        } else {
            if (grow < M) {
                int k = kk + ac;
                if (k + 3 < K) {
                    av = *(const float4*)(A + (size_t)grow * lda + k);
                } else {
#pragma unroll
                    for (int j = 0; j < 4; j++) {
                        int kj = k + j;
                        ((float*)&av)[j] = (kj < K) ? A[(size_t)grow * lda + kj] : 0.f;
                    }
                }
            }
        }
        sA[ac + 0][ar] = av.x; sA[ac + 1][ar] = av.y;
        sA[ac + 2][ar] = av.z; sA[ac + 3][ar] = av.w;

        float4 wv = make_float4(0.f, 0.f, 0.f, 0.f);
        if (kk + wk < K) wv = *(const float4*)(W + (size_t)(kk + wk) * 128 + wc);
        *(float4*)&sW[wk][wc] = wv;
        __syncthreads();

#pragma unroll
        for (int k = 0; k < 8; k++) {
            float4 a0 = *(float4*)&sA[k][ty * 8];
            float4 a1 = *(float4*)&sA[k][ty * 8 + 4];
            float4 b0 = *(float4*)&sW[k][tx * 8];
            float4 b1 = *(float4*)&sW[k][tx * 8 + 4];
            float ra[8] = {a0.x, a0.y, a0.z, a0.w, a1.x, a1.y, a1.z, a1.w};
            float rb[8] = {b0.x, b0.y, b0.z, b0.w, b1.x, b1.y, b1.z, b1.w};
#pragma unroll
            for (int i = 0; i < 8; i++)
#pragma unroll
                for (int j = 0; j < 8; j++) acc[i][j] += ra[i] * rb[j];
        }
        __syncthreads();
    }

    float ps[8], pq[8];
    if (MODE == 3) {
#pragma unroll
        for (int j = 0; j < 8; j++) { ps[j] = 0.f; pq[j] = 0.f; }
    }
#pragma unroll
    for (int i = 0; i < 8; i++) {
        int row = row0 + ty * 8 + i;
        if (row < M) {
#pragma unroll
            for (int j = 0; j < 8; j++) {
                int col = tx * 8 + j;
                float v = acc[i][j];
                if (MODE == 1) v += bias[col];
                if (MODE == 2) v += bias[col] + add[(size_t)row * DIM + col];
                if (MODE == 4) { v += bias[col]; v = (v > 0.f) ? v : 0.f; }
                if (MODE == 5) v += g_combB[col];
                C[(size_t)row * DIM + col] = v;
                if (MODE == 3) { ps[j] += v; pq[j] += v * v; }
            }
        }
    }
    if (MODE == 3) {
        if (tid < 128) { sS[tid] = 0.f; sQ[tid] = 0.f; }
        __syncthreads();
#pragma unroll
        for (int j = 0; j < 8; j++) {
            atomicAdd(&sS[tx * 8 + j], ps[j]);
            atomicAdd(&sQ[tx * 8 + j], pq[j]);
        }
        __syncthreads();
        if (tid < 128) {
            atomicAdd(&g_tsum[sidx * DIM + tid], (double)sS[tid]);
            atomicAdd(&g_tsumsq[sidx * DIM + tid], (double)sQ[tid]);
        }
    }
}

// =================== HMMA split-bf16 edge GEMM + fused epilogue =============
// y[320000,128] = path_feats @ pe_tgt_W + srcterm[sid]  (+ BN-stat accumulation)
#define LDE 72
#define LDW 36                        // words per row
#define EG_SMEM (4 * 128 * LDE * 2)   // Ah, Al, Bh, Bl = 73728 bytes

__device__ __forceinline__ void mma16816(float* c, const uint32_t* a, const uint32_t* b) {
    asm volatile(
        "mma.sync.aligned.m16n8k16.row.col.f32.bf16.bf16.f32 "
        "{%0,%1,%2,%3}, {%4,%5,%6,%7}, {%8,%9}, {%0,%1,%2,%3};"
        : "+f"(c[0]), "+f"(c[1]), "+f"(c[2]), "+f"(c[3])
        : "r"(a[0]), "r"(a[1]), "r"(a[2]), "r"(a[3]), "r"(b[0]), "r"(b[1]));
}
__device__ __forceinline__ uint32_t packbf(float x, float y) {
    union { __nv_bfloat162 b; uint32_t u; } c;
    c.b = __float22bfloat162_rn(make_float2(x, y));
    return c.u;
}

__global__ void __launch_bounds__(256, 2)
k_edge_gemm(const float* __restrict__ pf, const int* __restrict__ sid) {
    extern __shared__ char smem[];
    uint32_t* sAh = (uint32_t*)smem;
    uint32_t* sAl = sAh + 128 * LDW;
    uint32_t* sBh = sAl + 128 * LDW;
    uint32_t* sBl = sBh + 128 * LDW;
    int tid = threadIdx.x, wid = tid >> 5, lane = tid & 31;
    int g = lane >> 2, tg = lane & 3;
    int warpM = wid & 1, warpN = wid >> 1;     // warp tile 64x32
    int row0 = blockIdx.x * 128;

    float acc[4][4][4];
#pragma unroll
    for (int mt = 0; mt < 4; mt++)
#pragma unroll
        for (int nt = 0; nt < 4; nt++)
#pragma unroll
            for (int j = 0; j < 4; j++) acc[mt][nt][j] = 0.f;

    for (int kk = 0; kk < 256; kk += 64) {
        // ---- A convert: float4 loads, packed bf16x2 stores ----
#pragma unroll
        for (int it = 0; it < 8; it++) {
            int idx = tid + it * 256;          // 2048 float4s
            int r = idx >> 4, cq = idx & 15;
            int k = kk + cq * 4;
            float4 a = make_float4(0.f, 0.f, 0.f, 0.f);
            if (k + 3 < EDIM)
                a = *(const float4*)(pf + (size_t)(row0 + r) * EDIM + k);
            uint32_t h01 = packbf(a.x, a.y), h23 = packbf(a.z, a.w);
            float fx, fy;
            fx = a.x - __bfloat162float(__ushort_as_bfloat16((uint16_t)h01));
            fy = a.y - __bfloat162float(__ushort_as_bfloat16((uint16_t)(h01 >> 16)));
            uint32_t l01 = packbf(fx, fy);
            fx = a.z - __bfloat162float(__ushort_as_bfloat16((uint16_t)h23));
            fy = a.w - __bfloat162float(__ushort_as_bfloat16((uint16_t)(h23 >> 16)));
            uint32_t l23 = packbf(fx, fy);
            int w = r * LDW + cq * 2;
            sAh[w] = h01; sAh[w + 1] = h23;
            sAl[w] = l01; sAl[w + 1] = l23;
        }
        // ---- B copy from precomputed bf16 (LDG.128 -> STS.128) ----
#pragma unroll
        for (int it = 0; it < 4; it++) {
            int idx = tid + it * 256;          // 1024 16B chunks
            int n = idx >> 3, j = idx & 7;
            const char* srch = (const char*)g_Bh + ((size_t)n * 256 + kk + j * 8) * 2;
            const char* srcl = (const char*)g_Bl + ((size_t)n * 256 + kk + j * 8) * 2;
            *(uint4*)(sBh + n * LDW + j * 4) = *(const uint4*)srch;
            *(uint4*)(sBl + n * LDW + j * 4) = *(const uint4*)srcl;
        }
        __syncthreads();

        // ---- MMA ----
#pragma unroll
        for (int ks = 0; ks < 4; ks++) {
            int kw = ks * 8;
            uint32_t bh[4][2], bl[4][2];
#pragma unroll
            for (int nt = 0; nt < 4; nt++) {
                int n = warpN * 32 + nt * 8 + g;
                int o = n * LDW + kw + tg;
                bh[nt][0] = sBh[o]; bh[nt][1] = sBh[o + 4];
                bl[nt][0] = sBl[o]; bl[nt][1] = sBl[o + 4];
            }
#pragma unroll
            for (int mt = 0; mt < 4; mt++) {
                int m = warpM * 64 + mt * 16;
                int o0 = (m + g) * LDW + kw + tg;
                int o1 = (m + g + 8) * LDW + kw + tg;
                uint32_t ah[4] = {sAh[o0], sAh[o1], sAh[o0 + 4], sAh[o1 + 4]};
                uint32_t al[4] = {sAl[o0], sAl[o1], sAl[o0 + 4], sAl[o1 + 4]};
#pragma unroll
                for (int nt = 0; nt < 4; nt++) {
                    mma16816(acc[mt][nt], ah, bh[nt]);
                    mma16816(acc[mt][nt], ah, bl[nt]);
                    mma16816(acc[mt][nt], al, bh[nt]);
                }
            }
        }
        __syncthreads();
    }

    // ---- fused epilogue: y = acc + srcterm[sid[r]], store, BN stats ----
    float s_loc[4][2], q_loc[4][2];
#pragma unroll
    for (int nt = 0; nt < 4; nt++) {
        s_loc[nt][0] = s_loc[nt][1] = 0.f;
        q_loc[nt][0] = q_loc[nt][1] = 0.f;
    }
#pragma unroll
    for (int mt = 0; mt < 4; mt++) {
        int r0 = row0 + warpM * 64 + mt * 16 + g;
        const float* st0 = g_srcterm + (size_t)sid[r0] * DIM;
        const float* st1 = g_srcterm + (size_t)sid[r0 + 8] * DIM;
#pragma unroll
        for (int nt = 0; nt < 4; nt++) {
            int n = warpN * 32 + nt * 8 + 2 * tg;
            float2 e0 = *(const float2*)(st0 + n);
            float2 e1 = *(const float2*)(st1 + n);
            float y00 = acc[mt][nt][0] + e0.x, y01 = acc[mt][nt][1] + e0.y;
            float y10 = acc[mt][nt][2] + e1.x, y11 = acc[mt][nt][3] + e1.y;
            *(float2*)(g_xg + (size_t)r0 * DIM + n) = make_float2(y00, y01);
            *(float2*)(g_xg + (size_t)(r0 + 8) * DIM + n) = make_float2(y10, y11);
            s_loc[nt][0] += y00 + y10; s_loc[nt][1] += y01 + y11;
            q_loc[nt][0] += y00 * y00 + y10 * y10;
            q_loc[nt][1] += y01 * y01 + y11 * y11;
        }
    }
    __syncthreads();                       // tiles dead; reuse smem
    float* sS = (float*)smem;
    float* sQ = sS + 128;
    if (tid < 128) { sS[tid] = 0.f; sQ[tid] = 0.f; }
    __syncthreads();
#pragma unroll
    for (int nt = 0; nt < 4; nt++) {
        int n = warpN * 32 + nt * 8 + 2 * tg;
        atomicAdd(&sS[n], s_loc[nt][0]);
        atomicAdd(&sS[n + 1], s_loc[nt][1]);
        atomicAdd(&sQ[n], q_loc[nt][0]);
        atomicAdd(&sQ[n + 1], q_loc[nt][1]);
    }
    __syncthreads();
    if (tid < 128) {
        int bkt = (blockIdx.x & 31) * DIM + tid;
        atomicAdd(&g_psumB[bkt], (double)sS[tid]);
        atomicAdd(&g_psumsqB[bkt], (double)sQ[tid]);
    }
}

// ---------------- BN coefficient finalization -------------------------------
__global__ void k_coef1(const float* __restrict__ bng, const float* __restrict__ bnb,
                        const float* __restrict__ psb, const float* __restrict__ ptb) {
    int t = blockIdx.x * blockDim.x + threadIdx.x;
    if (t < 3 * DIM) {
        double mean = g_tsum[t] / NSRC;
        double var = g_tsumsq[t] / NSRC - mean * mean;
        float a = bng[t] * rsqrtf((float)var + BN_EPS);
        g_ta[t] = a;
        g_tc[t] = bnb[t] - a * (float)mean;
    }
    if (t < DIM) g_combB[t] = psb[t] + ptb[t];
}

__global__ void k_coef2(const float* __restrict__ peg, const float* __restrict__ peb) {
    int t = threadIdx.x;
    double s = 0.0, q = 0.0;
#pragma unroll
    for (int b2 = 0; b2 < 32; b2++) {
        s += g_psumB[b2 * DIM + t];
        q += g_psumsqB[b2 * DIM + t];
    }
    double mean = s / NEDGE;
    double var = q / NEDGE - mean * mean;
    float a = peg[t] * rsqrtf((float)var + BN_EPS);
    g_peA[t] = a;
    g_peC[t] = peb[t] - a * (float)mean;
}

// ---------------- scores (y already includes srcterm) ------------------------
__global__ void k_scores(const float* __restrict__ sw) {
    int w = (blockIdx.x * blockDim.x + threadIdx.x) >> 5;
    int lane = threadIdx.x & 31;
    int e0 = w * 64;
    float a[4], c4[4], wv[4];
#pragma unroll
    for (int j = 0; j < 4; j++) {
        int cc = lane + 32 * j;
        a[j] = g_peA[cc]; c4[j] = g_peC[cc]; wv[j] = sw[cc];
    }
    for (int e = e0; e < e0 + 64; e++) {
        const float* yr = g_xg + (size_t)e * DIM;
        float p = 0.f;
#pragma unroll
        for (int j = 0; j < 4; j++) {
            float v = a[j] * yr[lane + 32 * j] + c4[j];
            v = (v > 0.f) ? v : 0.f;
            p += v * wv[j];
        }
#pragma unroll
        for (int o = 16; o; o >>= 1) p += __shfl_xor_sync(0xffffffffu, p, o);
        if (lane == 0) g_scores[e] = p;
    }
}

// ---------------- top-k ------------------------------------------------------
__device__ __forceinline__ bool kbetter(float s1, int i1, float s2, int i2) {
    return (s1 > s2) || (s1 == s2 && i1 < i2);
}
__device__ __forceinline__ void top_insert(float* bs, int* bi, float v, int e) {
    if (!kbetter(v, e, bs[TOPN - 1], bi[TOPN - 1])) return;
    int p = TOPN - 1;
    while (p > 0 && kbetter(v, e, bs[p - 1], bi[p - 1])) {
        bs[p] = bs[p - 1]; bi[p] = bi[p - 1]; p--;
    }
    bs[p] = v; bi[p] = e;
}

__global__ void k_top_a() {
    float bs[TOPN]; int bi[TOPN];
#pragma unroll
    for (int j = 0; j < TOPN; j++) { bs[j] = -1e30f; bi[j] = 0x7fffffff; }
    int t = blockIdx.x * 256 + threadIdx.x;
    for (int e = t; e < NEDGE; e += 128 * 256) {
        top_insert(bs, bi, g_scores[e], e);
    }
    __shared__ float ss[256 * TOPN];
    __shared__ int si[256 * TOPN];
#pragma unroll
    for (int j = 0; j < TOPN; j++) {
        ss[threadIdx.x * TOPN + j] = bs[j];
        si[threadIdx.x * TOPN + j] = bi[j];
    }
    __syncthreads();
    if (threadIdx.x == 0) {
        float cs[TOPN]; int ci[TOPN];
#pragma unroll
        for (int j = 0; j < TOPN; j++) { cs[j] = -1e30f; ci[j] = 0x7fffffff; }
        for (int k = 0; k < 256 * TOPN; k++) top_insert(cs, ci, ss[k], si[k]);
        for (int j = 0; j < TOPN; j++) {
            g_cs[blockIdx.x * TOPN + j] = cs[j];
            g_ci[blockIdx.x * TOPN + j] = ci[j];
        }
    }
}

__global__ void k_top_b(float* __restrict__ out) {
    if (threadIdx.x == 0) {
        float cs[TOPN]; int ci[TOPN];
#pragma unroll
        for (int j = 0; j < TOPN; j++) { cs[j] = -1e30f; ci[j] = 0x7fffffff; }
        for (int k = 0; k < 128 * TOPN; k++) top_insert(cs, ci, g_cs[k], g_ci[k]);
        for (int j = 0; j < TOPN; j++) {
            out[(size_t)NSRC * DIM + j] = cs[j];
            out[(size_t)NSRC * DIM + TOPN + j] = (float)ci[j];
        }
    }
}

// ---------------- host entry -------------------------------------------------
extern "C" void kernel_launch(void* const* d_in, const int* in_sizes, int n_in,
                              void* d_out, int out_size) {
    bool dictorder = (in_sizes[2] == NEDGE);
    const float* paths = (const float*)d_in[0];
    const float* pf    = (const float*)d_in[1];
    const int*   sid   = (const int*)d_in[dictorder ? 2 : 19];
    int b = dictorder ? 3 : 2;
    const float* cew = (const float*)d_in[b + 0];
    const float* ceb = (const float*)d_in[b + 1];
    const float* w1  = (const float*)d_in[b + 2];
    const float* bng = (const float*)d_in[b + 3];
    const float* bnb = (const float*)d_in[b + 4];
    const float* w2  = (const float*)d_in[b + 5];
    const float* l1W = (const float*)d_in[b + 6];
    const float* l1b = (const float*)d_in[b + 7];
    const float* l2W = (const float*)d_in[b + 8];
    const float* l2b = (const float*)d_in[b + 9];
    const float* psW = (const float*)d_in[b + 10];
    const float* psb = (const float*)d_in[b + 11];
    const float* ptW = (const float*)d_in[b + 12];
    const float* ptb = (const float*)d_in[b + 13];
    const float* peg = (const float*)d_in[b + 14];
    const float* peb = (const float*)d_in[b + 15];
    const float* sw  = (const float*)d_in[b + 16];
    float* out = (float*)d_out;

    void *p_agg, *p_Wc, *p_H, *p_T, *p_h2, *p_srcterm;
    cudaGetSymbolAddress(&p_agg, g_agg);
    cudaGetSymbolAddress(&p_Wc, g_Wc);
    cudaGetSymbolAddress(&p_H, g_H);
    cudaGetSymbolAddress(&p_T, g_T);
    cudaGetSymbolAddress(&p_h2, g_h2);
    cudaGetSymbolAddress(&p_srcterm, g_srcterm);
    float* agg = (float*)p_agg;
    float* Wc = (float*)p_Wc;
    float* H = (float*)p_H;
    float* T = (float*)p_T;
    float* h2 = (float*)p_h2;
    float* srcterm = (float*)p_srcterm;

    cudaFuncSetAttribute(k_edge_gemm, cudaFuncAttributeMaxDynamicSharedMemorySize, EG_SMEM);

    const int NODE_BLKS = (NSRC + 127) / 128;   // 79

    k_reset<<<40, 256>>>();
    k_hist<<<(NEDGE + 255) / 256, 256>>>(sid);
    k_scan<<<1, 1024>>>();
    k_scatter<<<(NEDGE + 255) / 256, 256>>>(sid);
    k_prepB<<<128, 256>>>(ptW);
    k_agg<<<(NSRC * 32 + 255) / 256, 256>>>(pf);

    // Wc_i = W2_i @ L1_i (batched over y)
    gemm128<0><<<dim3(1, 3), 256>>>(w2, DIM, DIM, DIM, (long)DIM * DIM,
                                    l1W, (long)DIM * DIM, nullptr, 0, nullptr,
                                    Wc, (long)DIM * DIM);
    // H_i = paths + agg @ We_i + b_i  (batched)
    gemm128<2><<<dim3(NODE_BLKS, 3), 256>>>(agg, NSRC, EDIM, EDIM, 0L,
                                            cew, (long)EDIM * DIM, ceb, DIM, paths,
                                            H, (long)NSRC * DIM);
    // T_i = H_i @ W1_i (+ BN stats)  (batched)
    gemm128<3><<<dim3(NODE_BLKS, 3), 256>>>(H, NSRC, DIM, DIM, (long)NSRC * DIM,
                                            w1, (long)DIM * DIM, nullptr, 0, nullptr,
                                            T, (long)NSRC * DIM);
    k_coef1<<<2, 256>>>(bng, bnb, psb, ptb);

    // h2 = relu(concat(relu(BN(T_i))) @ Wc + lin1_b)
    gemm128<4><<<dim3(NODE_BLKS, 1), 256>>>(nullptr, NSRC, 3 * DIM, 0, 0L,
                                            Wc, 0L, l1b, 0, nullptr, h2, 0L);
    // node_emb -> d_out
    gemm128<1><<<dim3(NODE_BLKS, 1), 256>>>(h2, NSRC, DIM, DIM, 0L,
                                            l2W, 0L, l2b, 0, nullptr, out, 0L);
    // srcterm = node_emb @ pe_src_W + (pe_src_b + pe_tgt_b)
    gemm128<5><<<dim3(NODE_BLKS, 1), 256>>>(out, NSRC, DIM, DIM, 0L,
                                            psW, 0L, nullptr, 0, nullptr, srcterm, 0L);

    // edge GEMM (HMMA split-bf16) with fused srcterm add + BN stats
    k_edge_gemm<<<NEDGE / 128, 256, EG_SMEM>>>(pf, sid);

    k_coef2<<<1, 128>>>(peg, peb);
    k_scores<<<NEDGE / 512, 256>>>(sw);
    k_top_a<<<128, 256>>>();
    k_top_b<<<1, 32>>>(out);
}

// round 11
// speedup vs baseline: 1.9641x; 1.1957x over previous
#include <cuda_runtime.h>
#include <cuda_bf16.h>
#include <math.h>
#include <stdint.h>

#define NSRC 10000
#define NEDGE 320000
#define DIM 128
#define EDIM 236
#define TOPN 6
#define BN_EPS 1e-5f

// ---------------- scratch (device globals; no allocation allowed) ----------
__device__ float  g_agg[(size_t)NSRC * EDIM];
__device__ float  g_xg[(size_t)NEDGE * DIM];         // holds y = xg + srcterm[sid]
__device__ float  g_srcterm[(size_t)NSRC * DIM];
__device__ float  g_T[(size_t)3 * NSRC * DIM];
__device__ float  g_h2[(size_t)NSRC * DIM];
__device__ float  g_Wc[3 * DIM * DIM];               // [384][128] viewed flat
__device__ float  g_Wei1[3 * EDIM * DIM];            // We_i @ W1_i
__device__ float  g_cvec[3 * DIM];                   // b_i @ W1_i
__device__ float  g_scores[NEDGE];
__device__ int    g_cnt[NSRC];
__device__ int    g_off[NSRC + 1];
__device__ int    g_cur[NSRC];
__device__ int    g_order[NEDGE];
__device__ double g_tsum[3 * DIM], g_tsumsq[3 * DIM];
__device__ double g_psumB[32 * DIM], g_psumsqB[32 * DIM];
__device__ float  g_ta[3 * DIM], g_tc[3 * DIM];
__device__ float  g_peA[DIM], g_peC[DIM];
__device__ float  g_combB[DIM];
__device__ float  g_cs[128 * TOPN];
__device__ int    g_ci[128 * TOPN];
// pre-split bf16 weights, n-major [n][Kpad]
__device__ __nv_bfloat16 g_Bh[128 * 256],  g_Bl[128 * 256];     // pe_tgt_W
__device__ __nv_bfloat16 g_Wbh[3 * 128 * 384], g_Wbl[3 * 128 * 384]; // Wbig
__device__ __nv_bfloat16 g_Wch[128 * 384], g_Wcl[128 * 384];    // Wc concat
__device__ __nv_bfloat16 g_l2h[128 * 128], g_l2l[128 * 128];    // lin2
__device__ __nv_bfloat16 g_psh[128 * 128], g_psl[128 * 128];    // pe_src

// ---------------- small utility kernels ------------------------------------
__global__ void k_reset() {
    int t = blockIdx.x * blockDim.x + threadIdx.x;
    if (t < NSRC) g_cnt[t] = 0;
    if (t < 3 * DIM) { g_tsum[t] = 0.0; g_tsumsq[t] = 0.0; }
    if (t < 32 * DIM) { g_psumB[t] = 0.0; g_psumsqB[t] = 0.0; }
}

__global__ void k_hist(const int* __restrict__ sid) {
    int e = blockIdx.x * blockDim.x + threadIdx.x;
    if (e < NEDGE) atomicAdd(&g_cnt[sid[e]], 1);
}

__global__ void k_scan() {
    __shared__ int s[1024];
    int t = threadIdx.x;
    int base = t * 10;
    int loc[10];
    int acc = 0;
#pragma unroll
    for (int j = 0; j < 10; j++) {
        int idx = base + j;
        int v = (idx < NSRC) ? g_cnt[idx] : 0;
        loc[j] = acc; acc += v;
    }
    s[t] = acc;
    __syncthreads();
    for (int off = 1; off < 1024; off <<= 1) {
        int v = (t >= off) ? s[t - off] : 0;
        __syncthreads();
        s[t] += v;
        __syncthreads();
    }
    int pre = (t > 0) ? s[t - 1] : 0;
#pragma unroll
    for (int j = 0; j < 10; j++) {
        int idx = base + j;
        if (idx < NSRC) { g_off[idx] = pre + loc[j]; g_cur[idx] = pre + loc[j]; }
    }
    if (t == 0) g_off[NSRC] = NEDGE;
}

__global__ void k_scatter(const int* __restrict__ sid) {
    int e = blockIdx.x * blockDim.x + threadIdx.x;
    if (e < NEDGE) {
        int p = atomicAdd(&g_cur[sid[e]], 1);
        g_order[p] = e;
    }
}

__device__ __forceinline__ void splitbf(float v, __nv_bfloat16& h, __nv_bfloat16& l) {
    h = __float2bfloat16(v);
    l = __float2bfloat16(v - __bfloat162float(h));
}

// edge-B prep: pe_tgt_W[236,128] -> split bf16, n-major [n][256]
__global__ void k_prepB(const float* __restrict__ ptW) {
    int idx = blockIdx.x * 256 + threadIdx.x;
    if (idx >= 128 * 256) return;
    int k = idx >> 7, n = idx & 127;
    float b = (k < EDIM) ? ptW[(size_t)k * DIM + n] : 0.f;
    __nv_bfloat16 h, l; splitbf(b, h, l);
    g_Bh[n * 256 + k] = h;
    g_Bl[n * 256 + k] = l;
}

// Wbig prep: rows 0..235 = Wei1_i, 236..363 = W1_i, 364..383 = 0 -> [i][n][384]
__global__ void k_prepWbig(const float* __restrict__ w1) {
    int i = blockIdx.y;
    int idx = blockIdx.x * 256 + threadIdx.x;     // 49152 per i
    int n = idx / 384, k = idx % 384;
    float v = 0.f;
    if (k < EDIM) v = g_Wei1[i * EDIM * DIM + k * DIM + n];
    else if (k < EDIM + DIM) v = w1[i * DIM * DIM + (k - EDIM) * DIM + n];
    __nv_bfloat16 h, l; splitbf(v, h, l);
    g_Wbh[i * 128 * 384 + n * 384 + k] = h;
    g_Wbl[i * 128 * 384 + n * 384 + k] = l;
}

// generic weight prep: src [K][128] k-major fp32 -> dst [128][Kpad] split bf16
__global__ void k_prepWgen(const float* __restrict__ src, __nv_bfloat16* __restrict__ dh,
                           __nv_bfloat16* __restrict__ dl, int K, int Kpad) {
    int idx = blockIdx.x * 256 + threadIdx.x;
    if (idx >= 128 * Kpad) return;
    int n = idx / Kpad, k = idx % Kpad;
    float v = (k < K) ? src[(size_t)k * DIM + n] : 0.f;
    __nv_bfloat16 h, l; splitbf(v, h, l);
    dh[n * Kpad + k] = h;
    dl[n * Kpad + k] = l;
}

// c_i = b_i @ W1_i
__global__ void k_cvec(const float* __restrict__ ceb, const float* __restrict__ w1) {
    int i = blockIdx.x, n = threadIdx.x;
    float s = 0.f;
    for (int k = 0; k < DIM; k++)
        s += ceb[i * DIM + k] * w1[i * DIM * DIM + k * DIM + n];
    g_cvec[i * DIM + n] = s;
}

// one warp per node, float4 lanes (236 = 59 float4)
__global__ void k_agg(const float* __restrict__ pf) {
    int w = (blockIdx.x * blockDim.x + threadIdx.x) >> 5;
    int lane = threadIdx.x & 31;
    if (w >= NSRC) return;
    float4 a0 = make_float4(0.f, 0.f, 0.f, 0.f);
    float4 a1 = make_float4(0.f, 0.f, 0.f, 0.f);
    int s = g_off[w], e2 = g_off[w + 1];
    for (int p = s; p < e2; p++) {
        const float4* r = (const float4*)(pf + (size_t)g_order[p] * EDIM);
        float4 v = __ldg(r + lane);
        a0.x += fmaxf(v.x, 0.f); a0.y += fmaxf(v.y, 0.f);
        a0.z += fmaxf(v.z, 0.f); a0.w += fmaxf(v.w, 0.f);
        if (lane < 27) {
            float4 v2 = __ldg(r + 32 + lane);
            a1.x += fmaxf(v2.x, 0.f); a1.y += fmaxf(v2.y, 0.f);
            a1.z += fmaxf(v2.z, 0.f); a1.w += fmaxf(v2.w, 0.f);
        }
    }
    float4* outp = (float4*)(g_agg + (size_t)w * EDIM);
    outp[lane] = a0;
    if (lane < 27) outp[32 + lane] = a1;
}

// ---------------- small fp32 GEMM (C = A@W), batched over blockIdx.y --------
__global__ void __launch_bounds__(256)
gemm128(const float* __restrict__ A, int M, int K, int lda, long astr,
        const float* __restrict__ W, long wstr,
        float* __restrict__ C, long cstr) {
    int bz = blockIdx.y;
    A += (size_t)bz * astr;
    W += (size_t)bz * wstr;
    C += (size_t)bz * cstr;

    __shared__ float sA[8][128];
    __shared__ float sW[8][128];
    int tid = threadIdx.x;
    int row0 = blockIdx.x * 128;
    int tx = tid & 15, ty = tid >> 4;
    float acc[8][8];
#pragma unroll
    for (int i = 0; i < 8; i++)
#pragma unroll
        for (int j = 0; j < 8; j++) acc[i][j] = 0.f;

    int ar = tid >> 1;
    int ac = (tid & 1) * 4;
    int wk = (tid * 4) >> 7;
    int wc = (tid * 4) & 127;

    for (int kk = 0; kk < K; kk += 8) {
        float4 av = make_float4(0.f, 0.f, 0.f, 0.f);
        int grow = row0 + ar;
        if (grow < M) {
            int k = kk + ac;
            if (k + 3 < K) {
                av = *(const float4*)(A + (size_t)grow * lda + k);
            } else {
#pragma unroll
                for (int j = 0; j < 4; j++) {
                    int kj = k + j;
                    ((float*)&av)[j] = (kj < K) ? A[(size_t)grow * lda + kj] : 0.f;
                }
            }
        }
        sA[ac + 0][ar] = av.x; sA[ac + 1][ar] = av.y;
        sA[ac + 2][ar] = av.z; sA[ac + 3][ar] = av.w;

        float4 wv = make_float4(0.f, 0.f, 0.f, 0.f);
        if (kk + wk < K) wv = *(const float4*)(W + (size_t)(kk + wk) * 128 + wc);
        *(float4*)&sW[wk][wc] = wv;
        __syncthreads();

#pragma unroll
        for (int k = 0; k < 8; k++) {
            float4 a0 = *(float4*)&sA[k][ty * 8];
            float4 a1 = *(float4*)&sA[k][ty * 8 + 4];
            float4 b0 = *(float4*)&sW[k][tx * 8];
            float4 b1 = *(float4*)&sW[k][tx * 8 + 4];
            float ra[8] = {a0.x, a0.y, a0.z, a0.w, a1.x, a1.y, a1.z, a1.w};
            float rb[8] = {b0.x, b0.y, b0.z, b0.w, b1.x, b1.y, b1.z, b1.w};
#pragma unroll
            for (int i = 0; i < 8; i++)
#pragma unroll
                for (int j = 0; j < 8; j++) acc[i][j] += ra[i] * rb[j];
        }
        __syncthreads();
    }
#pragma unroll
    for (int i = 0; i < 8; i++) {
        int row = row0 + ty * 8 + i;
        if (row < M)
#pragma unroll
            for (int j = 0; j < 8; j++)
                C[(size_t)row * DIM + tx * 8 + j] = acc[i][j];
    }
}

// =================== shared HMMA split-bf16 machinery =======================
#define LDE 72
#define LDW 36
#define EG_SMEM (4 * 128 * LDE * 2)   // Ah, Al, Bh, Bl = 73728 bytes

__device__ __forceinline__ void mma16816(float* c, const uint32_t* a, const uint32_t* b) {
    asm volatile(
        "mma.sync.aligned.m16n8k16.row.col.f32.bf16.bf16.f32 "
        "{%0,%1,%2,%3}, {%4,%5,%6,%7}, {%8,%9}, {%0,%1,%2,%3};"
        : "+f"(c[0]), "+f"(c[1]), "+f"(c[2]), "+f"(c[3])
        : "r"(a[0]), "r"(a[1]), "r"(a[2]), "r"(a[3]), "r"(b[0]), "r"(b[1]));
}
__device__ __forceinline__ uint32_t packbf(float x, float y) {
    union { __nv_bfloat162 b; uint32_t u; } c;
    c.b = __float22bfloat162_rn(make_float2(x, y));
    return c.u;
}

// one 64-k chunk of MMAs — R6-proven fragment-load pattern (LDS.32)
__device__ __forceinline__ void mma_chunk(const uint32_t* sAh, const uint32_t* sAl,
                                          const uint32_t* sBh, const uint32_t* sBl,
                                          float acc[4][4][4],
                                          int g, int tg, int warpM, int warpN, int ksmax) {
    for (int ks = 0; ks < ksmax; ks++) {
        int kw = ks * 8;
        uint32_t bh[4][2], bl[4][2];
#pragma unroll
        for (int nt = 0; nt < 4; nt++) {
            int n = warpN * 32 + nt * 8 + g;
            int o = n * LDW + kw + tg;
            bh[nt][0] = sBh[o]; bh[nt][1] = sBh[o + 4];
            bl[nt][0] = sBl[o]; bl[nt][1] = sBl[o + 4];
        }
#pragma unroll
        for (int mt = 0; mt < 4; mt++) {
            int m = warpM * 64 + mt * 16;
            int o0 = (m + g) * LDW + kw + tg;
            int o1 = (m + g + 8) * LDW + kw + tg;
            uint32_t ah[4] = {sAh[o0], sAh[o1], sAh[o0 + 4], sAh[o1 + 4]};
            uint32_t al[4] = {sAl[o0], sAl[o1], sAl[o0 + 4], sAl[o1 + 4]};
#pragma unroll
            for (int nt = 0; nt < 4; nt++) {
                mma16816(acc[mt][nt], ah, bh[nt]);
                mma16816(acc[mt][nt], ah, bl[nt]);
                mma16816(acc[mt][nt], al, bh[nt]);
            }
        }
    }
}

__device__ __forceinline__ void store_split(uint32_t* sAh, uint32_t* sAl, int w, float4 a) {
    uint32_t h01 = packbf(a.x, a.y), h23 = packbf(a.z, a.w);
    float fx = a.x - __bfloat162float(__ushort_as_bfloat16((uint16_t)h01));
    float fy = a.y - __bfloat162float(__ushort_as_bfloat16((uint16_t)(h01 >> 16)));
    uint32_t l01 = packbf(fx, fy);
    fx = a.z - __bfloat162float(__ushort_as_bfloat16((uint16_t)h23));
    fy = a.w - __bfloat162float(__ushort_as_bfloat16((uint16_t)(h23 >> 16)));
    uint32_t l23 = packbf(fx, fy);
    sAh[w] = h01; sAh[w + 1] = h23;
    sAl[w] = l01; sAl[w + 1] = l23;
}

// =================== edge GEMM + fused epilogue =============================
__global__ void __launch_bounds__(256, 2)
k_edge_gemm(const float* __restrict__ pf, const int* __restrict__ sid) {
    extern __shared__ char smem[];
    uint32_t* sAh = (uint32_t*)smem;
    uint32_t* sAl = sAh + 128 * LDW;
    uint32_t* sBh = sAl + 128 * LDW;
    uint32_t* sBl = sBh + 128 * LDW;
    int tid = threadIdx.x, wid = tid >> 5, lane = tid & 31;
    int g = lane >> 2, tg = lane & 3;
    int warpM = wid & 1, warpN = wid >> 1;
    int row0 = blockIdx.x * 128;

    float acc[4][4][4];
#pragma unroll
    for (int mt = 0; mt < 4; mt++)
#pragma unroll
        for (int nt = 0; nt < 4; nt++)
#pragma unroll
            for (int j = 0; j < 4; j++) acc[mt][nt][j] = 0.f;

    for (int kk = 0; kk < 256; kk += 64) {
#pragma unroll
        for (int it = 0; it < 8; it++) {
            int idx = tid + it * 256;
            int r = idx >> 4, cq = idx & 15;
            int k = kk + cq * 4;
            float4 a = make_float4(0.f, 0.f, 0.f, 0.f);
            if (k + 3 < EDIM)
                a = *(const float4*)(pf + (size_t)(row0 + r) * EDIM + k);
            store_split(sAh, sAl, r * LDW + cq * 2, a);
        }
#pragma unroll
        for (int it = 0; it < 4; it++) {
            int idx = tid + it * 256;
            int n = idx >> 3, j = idx & 7;
            const char* srch = (const char*)g_Bh + ((size_t)n * 256 + kk + j * 8) * 2;
            const char* srcl = (const char*)g_Bl + ((size_t)n * 256 + kk + j * 8) * 2;
            *(uint4*)(sBh + n * LDW + j * 4) = *(const uint4*)srch;
            *(uint4*)(sBl + n * LDW + j * 4) = *(const uint4*)srcl;
        }
        __syncthreads();
        int ksmax = (kk == 192) ? 3 : 4;   // k 240..255 is all zero padding
        mma_chunk(sAh, sAl, sBh, sBl, acc, g, tg, warpM, warpN, ksmax);
        __syncthreads();
    }

    // fused epilogue: y = acc + srcterm[sid[r]], store, BN stats
    float s_loc[4][2], q_loc[4][2];
#pragma unroll
    for (int nt = 0; nt < 4; nt++) {
        s_loc[nt][0] = s_loc[nt][1] = 0.f;
        q_loc[nt][0] = q_loc[nt][1] = 0.f;
    }
#pragma unroll
    for (int mt = 0; mt < 4; mt++) {
        int r0 = row0 + warpM * 64 + mt * 16 + g;
        const float* st0 = g_srcterm + (size_t)sid[r0] * DIM;
        const float* st1 = g_srcterm + (size_t)sid[r0 + 8] * DIM;
#pragma unroll
        for (int nt = 0; nt < 4; nt++) {
            int n = warpN * 32 + nt * 8 + 2 * tg;
            float2 e0 = *(const float2*)(st0 + n);
            float2 e1 = *(const float2*)(st1 + n);
            float y00 = acc[mt][nt][0] + e0.x, y01 = acc[mt][nt][1] + e0.y;
            float y10 = acc[mt][nt][2] + e1.x, y11 = acc[mt][nt][3] + e1.y;
            *(float2*)(g_xg + (size_t)r0 * DIM + n) = make_float2(y00, y01);
            *(float2*)(g_xg + (size_t)(r0 + 8) * DIM + n) = make_float2(y10, y11);
            s_loc[nt][0] += y00 + y10; s_loc[nt][1] += y01 + y11;
            q_loc[nt][0] += y00 * y00 + y10 * y10;
            q_loc[nt][1] += y01 * y01 + y11 * y11;
        }
    }
    __syncthreads();
    float* sS = (float*)smem;
    float* sQ = sS + 128;
    if (tid < 128) { sS[tid] = 0.f; sQ[tid] = 0.f; }
    __syncthreads();
#pragma unroll
    for (int nt = 0; nt < 4; nt++) {
        int n = warpN * 32 + nt * 8 + 2 * tg;
        atomicAdd(&sS[n], s_loc[nt][0]);
        atomicAdd(&sS[n + 1], s_loc[nt][1]);
        atomicAdd(&sQ[n], q_loc[nt][0]);
        atomicAdd(&sQ[n + 1], q_loc[nt][1]);
    }
    __syncthreads();
    if (tid < 128) {
        int bkt = (blockIdx.x & 31) * DIM + tid;
        atomicAdd(&g_psumB[bkt], (double)sS[tid]);
        atomicAdd(&g_psumsqB[bkt], (double)sQ[tid]);
    }
}

// =================== generic node HMMA GEMM =================================
// AMODE 0: A = [A1(236) | A2(128)] concat (Kreal=364)
// AMODE 1: A = relu(ta*g_T+tc) Z-concat (Kreal=384)
// AMODE 2: A = A1 [M][Kreal], Kreal=128
// EMODE 0: C = acc + bias
// EMODE 1: C = relu(acc + bias)
// EMODE 2: C = acc + bias, accumulate col stats to g_tsum[blockIdx.y]
template <int AMODE, int EMODE>
__global__ void __launch_bounds__(256, 2)
k_nmma(const float* __restrict__ A1, const float* __restrict__ A2,
       int M, int Kreal, int Kpad,
       const __nv_bfloat16* __restrict__ Wh, const __nv_bfloat16* __restrict__ Wl,
       long wstr, const float* __restrict__ bias, long bstr,
       float* __restrict__ C, long cstr) {
    int bz = blockIdx.y;
    Wh += (size_t)bz * wstr; Wl += (size_t)bz * wstr;
    bias += (size_t)bz * bstr; C += (size_t)bz * cstr;

    extern __shared__ char smem[];
    uint32_t* sAh = (uint32_t*)smem;
    uint32_t* sAl = sAh + 128 * LDW;
    uint32_t* sBh = sAl + 128 * LDW;
    uint32_t* sBl = sBh + 128 * LDW;
    int tid = threadIdx.x, wid = tid >> 5, lane = tid & 31;
    int g = lane >> 2, tg = lane & 3;
    int warpM = wid & 1, warpN = wid >> 1;
    int row0 = blockIdx.x * 128;

    float acc[4][4][4];
#pragma unroll
    for (int mt = 0; mt < 4; mt++)
#pragma unroll
        for (int nt = 0; nt < 4; nt++)
#pragma unroll
            for (int j = 0; j < 4; j++) acc[mt][nt][j] = 0.f;

    for (int kk = 0; kk < Kpad; kk += 64) {
#pragma unroll
        for (int it = 0; it < 8; it++) {
            int idx = tid + it * 256;
            int r = idx >> 4, cq = idx & 15;
            int k = kk + cq * 4;
            int grow = row0 + r;
            float4 a = make_float4(0.f, 0.f, 0.f, 0.f);
            if (grow < M) {
                if (AMODE == 0) {
                    if (k < EDIM) a = *(const float4*)(A1 + (size_t)grow * EDIM + k);
                    else if (k < EDIM + DIM) a = *(const float4*)(A2 + (size_t)grow * DIM + (k - EDIM));
                } else if (AMODE == 1) {
                    int blk = k >> 7;
                    float4 t = *(const float4*)(g_T + ((size_t)(blk * NSRC + grow)) * DIM + (k & 127));
                    float4 ta = *(const float4*)(g_ta + k);
                    float4 tc = *(const float4*)(g_tc + k);
                    a.x = fmaxf(ta.x * t.x + tc.x, 0.f);
                    a.y = fmaxf(ta.y * t.y + tc.y, 0.f);
                    a.z = fmaxf(ta.z * t.z + tc.z, 0.f);
                    a.w = fmaxf(ta.w * t.w + tc.w, 0.f);
                } else {
                    if (k < Kreal) a = *(const float4*)(A1 + (size_t)grow * Kreal + k);
                }
            }
            store_split(sAh, sAl, r * LDW + cq * 2, a);
        }
#pragma unroll
        for (int it = 0; it < 4; it++) {
            int idx = tid + it * 256;
            int n = idx >> 3, j = idx & 7;
            const char* srch = (const char*)Wh + ((size_t)n * Kpad + kk + j * 8) * 2;
            const char* srcl = (const char*)Wl + ((size_t)n * Kpad + kk + j * 8) * 2;
            *(uint4*)(sBh + n * LDW + j * 4) = *(const uint4*)srch;
            *(uint4*)(sBl + n * LDW + j * 4) = *(const uint4*)srcl;
        }
        __syncthreads();
        int rem = (Kreal - kk + 15) >> 4;
        int ksmax = rem < 4 ? rem : 4;
        mma_chunk(sAh, sAl, sBh, sBl, acc, g, tg, warpM, warpN, ksmax);
        __syncthreads();
    }

    float s_loc[4][2], q_loc[4][2];
    if (EMODE == 2) {
#pragma unroll
        for (int nt = 0; nt < 4; nt++) {
            s_loc[nt][0] = s_loc[nt][1] = 0.f;
            q_loc[nt][0] = q_loc[nt][1] = 0.f;
        }
    }
#pragma unroll
    for (int mt = 0; mt < 4; mt++) {
        int r0 = row0 + warpM * 64 + mt * 16 + g;
        bool v0 = r0 < M, v1 = (r0 + 8) < M;
#pragma unroll
        for (int nt = 0; nt < 4; nt++) {
            int n = warpN * 32 + nt * 8 + 2 * tg;
            float b0 = bias[n], b1 = bias[n + 1];
            float y00 = acc[mt][nt][0] + b0, y01 = acc[mt][nt][1] + b1;
            float y10 = acc[mt][nt][2] + b0, y11 = acc[mt][nt][3] + b1;
            if (EMODE == 1) {
                y00 = fmaxf(y00, 0.f); y01 = fmaxf(y01, 0.f);
                y10 = fmaxf(y10, 0.f); y11 = fmaxf(y11, 0.f);
            }
            if (v0) *(float2*)(C + (size_t)r0 * DIM + n) = make_float2(y00, y01);
            if (v1) *(float2*)(C + (size_t)(r0 + 8) * DIM + n) = make_float2(y10, y11);
            if (EMODE == 2) {
                if (v0) { s_loc[nt][0] += y00; s_loc[nt][1] += y01;
                          q_loc[nt][0] += y00 * y00; q_loc[nt][1] += y01 * y01; }
                if (v1) { s_loc[nt][0] += y10; s_loc[nt][1] += y11;
                          q_loc[nt][0] += y10 * y10; q_loc[nt][1] += y11 * y11; }
            }
        }
    }
    if (EMODE == 2) {
        __syncthreads();
        float* sS = (float*)smem;
        float* sQ = sS + 128;
        if (tid < 128) { sS[tid] = 0.f; sQ[tid] = 0.f; }
        __syncthreads();
#pragma unroll
        for (int nt = 0; nt < 4; nt++) {
            int n = warpN * 32 + nt * 8 + 2 * tg;
            atomicAdd(&sS[n], s_loc[nt][0]);
            atomicAdd(&sS[n + 1], s_loc[nt][1]);
            atomicAdd(&sQ[n], q_loc[nt][0]);
            atomicAdd(&sQ[n + 1], q_loc[nt][1]);
        }
        __syncthreads();
        if (tid < 128) {
            atomicAdd(&g_tsum[bz * DIM + tid], (double)sS[tid]);
            atomicAdd(&g_tsumsq[bz * DIM + tid], (double)sQ[tid]);
        }
    }
}

// ---------------- BN coefficient finalization -------------------------------
__global__ void k_coef1(const float* __restrict__ bng, const float* __restrict__ bnb,
                        const float* __restrict__ psb, const float* __restrict__ ptb) {
    int t = blockIdx.x * blockDim.x + threadIdx.x;
    if (t < 3 * DIM) {
        double mean = g_tsum[t] / NSRC;
        double var = g_tsumsq[t] / NSRC - mean * mean;
        float a = bng[t] * rsqrtf((float)var + BN_EPS);
        g_ta[t] = a;
        g_tc[t] = bnb[t] - a * (float)mean;
    }
    if (t < DIM) g_combB[t] = psb[t] + ptb[t];
}

__global__ void k_coef2(const float* __restrict__ peg, const float* __restrict__ peb) {
    int t = threadIdx.x;
    double s = 0.0, q = 0.0;
#pragma unroll
    for (int b2 = 0; b2 < 32; b2++) {
        s += g_psumB[b2 * DIM + t];
        q += g_psumsqB[b2 * DIM + t];
    }
    double mean = s / NEDGE;
    double var = q / NEDGE - mean * mean;
    float a = peg[t] * rsqrtf((float)var + BN_EPS);
    g_peA[t] = a;
    g_peC[t] = peb[t] - a * (float)mean;
}

// ---------------- scores -----------------------------------------------------
__global__ void k_scores(const float* __restrict__ sw) {
    int w = (blockIdx.x * blockDim.x + threadIdx.x) >> 5;
    int lane = threadIdx.x & 31;
    int e0 = w * 64;
    float a[4], c4[4], wv[4];
#pragma unroll
    for (int j = 0; j < 4; j++) {
        int cc = lane + 32 * j;
        a[j] = g_peA[cc]; c4[j] = g_peC[cc]; wv[j] = sw[cc];
    }
    for (int e = e0; e < e0 + 64; e++) {
        const float* yr = g_xg + (size_t)e * DIM;
        float p = 0.f;
#pragma unroll
        for (int j = 0; j < 4; j++) {
            float v = a[j] * yr[lane + 32 * j] + c4[j];
            v = (v > 0.f) ? v : 0.f;
            p += v * wv[j];
        }
#pragma unroll
        for (int o = 16; o; o >>= 1) p += __shfl_xor_sync(0xffffffffu, p, o);
        if (lane == 0) g_scores[e] = p;
    }
}

// ---------------- top-k ------------------------------------------------------
__device__ __forceinline__ bool kbetter(float s1, int i1, float s2, int i2) {
    return (s1 > s2) || (s1 == s2 && i1 < i2);
}
__device__ __forceinline__ void top_insert(float* bs, int* bi, float v, int e) {
    if (!kbetter(v, e, bs[TOPN - 1], bi[TOPN - 1])) return;
    int p = TOPN - 1;
    while (p > 0 && kbetter(v, e, bs[p - 1], bi[p - 1])) {
        bs[p] = bs[p - 1]; bi[p] = bi[p - 1]; p--;
    }
    bs[p] = v; bi[p] = e;
}

__global__ void k_top_a() {
    float bs[TOPN]; int bi[TOPN];
#pragma unroll
    for (int j = 0; j < TOPN; j++) { bs[j] = -1e30f; bi[j] = 0x7fffffff; }
    int t = blockIdx.x * 256 + threadIdx.x;
    for (int e = t; e < NEDGE; e += 128 * 256) {
        top_insert(bs, bi, g_scores[e], e);
    }
    __shared__ float ss[256 * TOPN];
    __shared__ int si[256 * TOPN];
#pragma unroll
    for (int j = 0; j < TOPN; j++) {
        ss[threadIdx.x * TOPN + j] = bs[j];
        si[threadIdx.x * TOPN + j] = bi[j];
    }
    __syncthreads();
    if (threadIdx.x == 0) {
        float cs[TOPN]; int ci[TOPN];
#pragma unroll
        for (int j = 0; j < TOPN; j++) { cs[j] = -1e30f; ci[j] = 0x7fffffff; }
        for (int k = 0; k < 256 * TOPN; k++) top_insert(cs, ci, ss[k], si[k]);
        for (int j = 0; j < TOPN; j++) {
            g_cs[blockIdx.x * TOPN + j] = cs[j];
            g_ci[blockIdx.x * TOPN + j] = ci[j];
        }
    }
}

__global__ void k_top_b(float* __restrict__ out) {
    if (threadIdx.x == 0) {
        float cs[TOPN]; int ci[TOPN];
#pragma unroll
        for (int j = 0; j < TOPN; j++) { cs[j] = -1e30f; ci[j] = 0x7fffffff; }
        for (int k = 0; k < 128 * TOPN; k++) top_insert(cs, ci, g_cs[k], g_ci[k]);
        for (int j = 0; j < TOPN; j++) {
            out[(size_t)NSRC * DIM + j] = cs[j];
            out[(size_t)NSRC * DIM + TOPN + j] = (float)ci[j];
        }
    }
}

// ---------------- host entry -------------------------------------------------
extern "C" void kernel_launch(void* const* d_in, const int* in_sizes, int n_in,
                              void* d_out, int out_size) {
    bool dictorder = (in_sizes[2] == NEDGE);
    const float* paths = (const float*)d_in[0];
    const float* pf    = (const float*)d_in[1];
    const int*   sid   = (const int*)d_in[dictorder ? 2 : 19];
    int b = dictorder ? 3 : 2;
    const float* cew = (const float*)d_in[b + 0];
    const float* ceb = (const float*)d_in[b + 1];
    const float* w1  = (const float*)d_in[b + 2];
    const float* bng = (const float*)d_in[b + 3];
    const float* bnb = (const float*)d_in[b + 4];
    const float* w2  = (const float*)d_in[b + 5];
    const float* l1W = (const float*)d_in[b + 6];
    const float* l1b = (const float*)d_in[b + 7];
    const float* l2W = (const float*)d_in[b + 8];
    const float* l2b = (const float*)d_in[b + 9];
    const float* psW = (const float*)d_in[b + 10];
    const float* psb = (const float*)d_in[b + 11];
    const float* ptW = (const float*)d_in[b + 12];
    const float* ptb = (const float*)d_in[b + 13];
    const float* peg = (const float*)d_in[b + 14];
    const float* peb = (const float*)d_in[b + 15];
    const float* sw  = (const float*)d_in[b + 16];
    float* out = (float*)d_out;

    // resolve ALL device symbols used as kernel arguments (host shadow is UB!)
    void *p_agg, *p_Wc, *p_Wei1, *p_T, *p_h2, *p_srcterm, *p_cvec, *p_combB;
    void *p_Wbh, *p_Wbl, *p_Wch, *p_Wcl, *p_l2h, *p_l2l, *p_psh, *p_psl;
    cudaGetSymbolAddress(&p_agg, g_agg);
    cudaGetSymbolAddress(&p_Wc, g_Wc);
    cudaGetSymbolAddress(&p_Wei1, g_Wei1);
    cudaGetSymbolAddress(&p_T, g_T);
    cudaGetSymbolAddress(&p_h2, g_h2);
    cudaGetSymbolAddress(&p_srcterm, g_srcterm);
    cudaGetSymbolAddress(&p_cvec, g_cvec);
    cudaGetSymbolAddress(&p_combB, g_combB);
    cudaGetSymbolAddress(&p_Wbh, g_Wbh);
    cudaGetSymbolAddress(&p_Wbl, g_Wbl);
    cudaGetSymbolAddress(&p_Wch, g_Wch);
    cudaGetSymbolAddress(&p_Wcl, g_Wcl);
    cudaGetSymbolAddress(&p_l2h, g_l2h);
    cudaGetSymbolAddress(&p_l2l, g_l2l);
    cudaGetSymbolAddress(&p_psh, g_psh);
    cudaGetSymbolAddress(&p_psl, g_psl);
    const __nv_bfloat16* Wbh = (const __nv_bfloat16*)p_Wbh;
    const __nv_bfloat16* Wbl = (const __nv_bfloat16*)p_Wbl;
    const __nv_bfloat16* Wch = (const __nv_bfloat16*)p_Wch;
    const __nv_bfloat16* Wcl = (const __nv_bfloat16*)p_Wcl;
    const __nv_bfloat16* l2h = (const __nv_bfloat16*)p_l2h;
    const __nv_bfloat16* l2l = (const __nv_bfloat16*)p_l2l;
    const __nv_bfloat16* psh = (const __nv_bfloat16*)p_psh;
    const __nv_bfloat16* psl = (const __nv_bfloat16*)p_psl;

    cudaFuncSetAttribute(k_edge_gemm, cudaFuncAttributeMaxDynamicSharedMemorySize, EG_SMEM);
    cudaFuncSetAttribute(k_nmma<0, 2>, cudaFuncAttributeMaxDynamicSharedMemorySize, EG_SMEM);
    cudaFuncSetAttribute(k_nmma<1, 1>, cudaFuncAttributeMaxDynamicSharedMemorySize, EG_SMEM);
    cudaFuncSetAttribute(k_nmma<2, 0>, cudaFuncAttributeMaxDynamicSharedMemorySize, EG_SMEM);

    const int NODE_BLKS = (NSRC + 127) / 128;   // 79

    k_reset<<<40, 256>>>();
    k_hist<<<(NEDGE + 255) / 256, 256>>>(sid);
    k_scan<<<1, 1024>>>();
    k_scatter<<<(NEDGE + 255) / 256, 256>>>(sid);
    k_prepB<<<128, 256>>>(ptW);
    k_agg<<<(NSRC * 32 + 255) / 256, 256>>>(pf);

    // small fp32 folds: Wc_i = W2_i @ L1_i ; Wei1_i = We_i @ W1_i ; c_i = b_i @ W1_i
    gemm128<<<dim3(1, 3), 256>>>(w2, DIM, DIM, DIM, (long)DIM * DIM,
                                 l1W, (long)DIM * DIM, (float*)p_Wc, (long)DIM * DIM);
    gemm128<<<dim3(2, 3), 256>>>(cew, EDIM, DIM, DIM, (long)EDIM * DIM,
                                 w1, (long)DIM * DIM, (float*)p_Wei1, (long)EDIM * DIM);
    k_cvec<<<3, 128>>>(ceb, w1);

    // pre-split weights to bf16 n-major (dst pointers symbol-resolved!)
    k_prepWbig<<<dim3(192, 3), 256>>>(w1);
    k_prepWgen<<<192, 256>>>((const float*)p_Wc, (__nv_bfloat16*)p_Wch,
                             (__nv_bfloat16*)p_Wcl, 384, 384);
    k_prepWgen<<<64, 256>>>(l2W, (__nv_bfloat16*)p_l2h, (__nv_bfloat16*)p_l2l, 128, 128);
    k_prepWgen<<<64, 256>>>(psW, (__nv_bfloat16*)p_psh, (__nv_bfloat16*)p_psl, 128, 128);

    // T_cat = [agg|paths] @ Wbig_i + c_i  (+ BN stats)
    k_nmma<0, 2><<<dim3(NODE_BLKS, 3), 256, EG_SMEM>>>(
        (const float*)p_agg, paths, NSRC, EDIM + DIM, 384,
        Wbh, Wbl, (long)128 * 384, (const float*)p_cvec, DIM,
        (float*)p_T, (long)NSRC * DIM);
    k_coef1<<<2, 256>>>(bng, bnb, psb, ptb);

    // h2 = relu(Z @ Wc + l1b)
    k_nmma<1, 1><<<dim3(NODE_BLKS, 1), 256, EG_SMEM>>>(
        nullptr, nullptr, NSRC, 384, 384,
        Wch, Wcl, 0L, l1b, 0L, (float*)p_h2, 0L);
    // node_emb = h2 @ l2W + l2b -> out
    k_nmma<2, 0><<<dim3(NODE_BLKS, 1), 256, EG_SMEM>>>(
        (const float*)p_h2, nullptr, NSRC, 128, 128,
        l2h, l2l, 0L, l2b, 0L, out, 0L);
    // srcterm = node_emb @ psW + (psb + ptb)
    k_nmma<2, 0><<<dim3(NODE_BLKS, 1), 256, EG_SMEM>>>(
        out, nullptr, NSRC, 128, 128,
        psh, psl, 0L, (const float*)p_combB, 0L, (float*)p_srcterm, 0L);

    // edge GEMM (HMMA split-bf16) with fused srcterm add + BN stats
    k_edge_gemm<<<NEDGE / 128, 256, EG_SMEM>>>(pf, sid);

    k_coef2<<<1, 128>>>(peg, peb);
    k_scores<<<NEDGE / 512, 256>>>(sw);
    k_top_a<<<128, 256>>>();
    k_top_b<<<1, 32>>>(out);
}